// round 12
// baseline (speedup 1.0000x reference)
#include <cuda_runtime.h>
#include <cuda_bf16.h>
#include <math.h>

#define BB 256
#define TT 2048
typedef unsigned long long ull;
typedef unsigned int u32;

__device__ __nv_bfloat16 g_y1h[(size_t)BB * TT * 256];
__device__ __nv_bfloat16 g_y1l[(size_t)BB * TT * 256];
__device__ __nv_bfloat16 g_w2h[512 * 256];
__device__ __nv_bfloat16 g_w2l[512 * 256];
__device__ __nv_bfloat16 g_w3h[128 * 128];
__device__ __nv_bfloat16 g_w3l[128 * 128];
__device__ __nv_bfloat16 g_y2h[(size_t)BB * TT * 128];
__device__ __nv_bfloat16 g_y2l[(size_t)BB * TT * 128];
__device__ float g_xg2[(size_t)BB * TT * 512];
__device__ float g_xg3[(size_t)BB * TT * 128];
__device__ float g_sum3[BB * 32];

__device__ __forceinline__ float mysig(float v){ return __fdividef(1.0f, 1.0f + __expf(-v)); }
__device__ __forceinline__ float mytanh(float v){
    float e = __expf(2.0f * v);
    return 1.0f - 2.0f * __fdividef(1.0f, 1.0f + e);
}
__device__ __forceinline__ void upk(ull v, float& lo, float& hi){
    asm("mov.b64 {%0, %1}, %2;" : "=f"(lo), "=f"(hi) : "l"(v));
}
__device__ __forceinline__ void fma2(ull& d, ull a, ull b){
    asm("fma.rn.f32x2 %0, %1, %2, %0;" : "+l"(d) : "l"(a), "l"(b));
}
__device__ __forceinline__ void mma_bf16(float* d, const u32* a, const u32* b){
    asm volatile("mma.sync.aligned.m16n8k16.row.col.f32.bf16.bf16.f32 "
        "{%0,%1,%2,%3}, {%4,%5,%6,%7}, {%8,%9}, {%0,%1,%2,%3};"
        : "+f"(d[0]), "+f"(d[1]), "+f"(d[2]), "+f"(d[3])
        : "r"(a[0]), "r"(a[1]), "r"(a[2]), "r"(a[3]), "r"(b[0]), "r"(b[1]));
}
__device__ __forceinline__ u32 hi2(float a, float b){
    return (u32)__bfloat16_as_ushort(__float2bfloat16(a))
         | ((u32)__bfloat16_as_ushort(__float2bfloat16(b)) << 16);
}
__device__ __forceinline__ u32 lo2(float a, float b){
    float ra = a - __bfloat162float(__float2bfloat16(a));
    float rb = b - __bfloat162float(__float2bfloat16(b));
    return hi2(ra, rb);
}
__device__ __forceinline__ u32 s2u(const void* p){
    u32 a; asm("{ .reg .u64 t; cvta.to.shared.u64 t, %1; cvt.u32.u64 %0, t; }" : "=r"(a) : "l"(p));
    return a;
}
__device__ __forceinline__ void ldm4(u32* r, const void* p){
    asm volatile("ldmatrix.sync.aligned.m8n8.x4.shared.b16 {%0,%1,%2,%3}, [%4];"
        : "=r"(r[0]), "=r"(r[1]), "=r"(r[2]), "=r"(r[3]) : "r"(s2u(p)));
}

// ============ Layer 1 via mma.sync ============
#define L1_ALO  0
#define L1_BHI  131072
#define L1_BLO  133120
#define L1_GAT  135168     // float[512][5] = 10240
#define L1_SMEM 145408

__global__ __launch_bounds__(512, 1) void lstm1_mma(
    const float* __restrict__ x, const float* __restrict__ Wih,
    const float* __restrict__ Whh, const float* __restrict__ bih,
    const float* __restrict__ bhh,
    __nv_bfloat16* __restrict__ y1h, __nv_bfloat16* __restrict__ y1l)
{
    extern __shared__ char sm[];
    u32*   sALo = (u32*)(sm + L1_ALO);
    float* sgat = (float*)(sm + L1_GAT);

    const int tid = threadIdx.x, w = tid >> 5, l = tid & 31;
    const int g = l >> 2, tq = l & 3;
    const int dir = blockIdx.y, bg0 = blockIdx.x * 4;
    const float* WD = Whh + (size_t)dir * 512 * 128;

    u32 Ah[2][8][4];
    #pragma unroll
    for (int mt = 0; mt < 2; mt++)
        #pragma unroll
        for (int ks = 0; ks < 8; ks++) {
            int R = 32 * w + 16 * mt + g, C = 16 * ks + 2 * tq;
            const float* p0 = WD + (size_t)R * 128 + C;
            const float* p1 = WD + (size_t)(R + 8) * 128 + C;
            Ah[mt][ks][0] = hi2(p0[0], p0[1]);
            Ah[mt][ks][1] = hi2(p1[0], p1[1]);
            Ah[mt][ks][2] = hi2(p0[8], p0[9]);
            Ah[mt][ks][3] = hi2(p1[8], p1[9]);
            u32* q = sALo + (((w * 2 + mt) * 8 + ks) * 32 + l) * 4;
            q[0] = lo2(p0[0], p0[1]);
            q[1] = lo2(p1[0], p1[1]);
            q[2] = lo2(p0[8], p0[9]);
            q[3] = lo2(p1[8], p1[9]);
        }
    for (int i = tid; i < 1024; i += 512) ((u32*)(sm + L1_BHI))[i] = 0;

    const int cb = tid >> 7, j = tid & 127;
    float bias4[4], wx04[4], wx14[4];
    #pragma unroll
    for (int q = 0; q < 4; q++) {
        int rq = j + 128 * q;
        bias4[q] = bih[dir * 512 + rq] + bhh[dir * 512 + rq];
        wx04[q] = Wih[dir * 1024 + rq * 2];
        wx14[q] = Wih[dir * 1024 + rq * 2 + 1];
    }
    const u32 bko = (u32)(j >> 4) * 256 + (u32)(4 * cb + ((j & 7) >> 1)) * 8
                  + (u32)((j >> 3) & 1) * 4 + (u32)(j & 1) * 2;
    float cc = 0.0f;
    __syncthreads();

    for (int s = 0; s < TT; s++) {
        const int t = dir ? (TT - 1 - s) : s;
        float2 xv = __ldg((const float2*)(x + ((size_t)(bg0 + cb) * TT + t) * 2));

        float Da[4]={0,0,0,0}, Db[4]={0,0,0,0}, Dc[4]={0,0,0,0};
        float Ea[4]={0,0,0,0}, Eb[4]={0,0,0,0}, Ec[4]={0,0,0,0};
        #pragma unroll
        for (int ks = 0; ks < 8; ks++) {
            uint2 bh = *(const uint2*)(sm + L1_BHI + ks * 256 + l * 8);
            uint2 bl = *(const uint2*)(sm + L1_BLO + ks * 256 + l * 8);
            uint4 al0 = *(const uint4*)(sALo + (((w * 2 + 0) * 8 + ks) * 32 + l) * 4);
            uint4 al1 = *(const uint4*)(sALo + (((w * 2 + 1) * 8 + ks) * 32 + l) * 4);
            mma_bf16(Da, Ah[0][ks], &bh.x);
            mma_bf16(Db, (const u32*)&al0, &bh.x);
            mma_bf16(Dc, Ah[0][ks], &bl.x);
            mma_bf16(Ea, Ah[1][ks], &bh.x);
            mma_bf16(Eb, (const u32*)&al1, &bh.x);
            mma_bf16(Ec, Ah[1][ks], &bl.x);
        }
        if (tq < 2) {
            int r0 = 32 * w + g;
            sgat[r0 * 5 + 2*tq]          = Da[0] + Db[0] + Dc[0];
            sgat[r0 * 5 + 2*tq + 1]      = Da[1] + Db[1] + Dc[1];
            sgat[(r0+8) * 5 + 2*tq]      = Da[2] + Db[2] + Dc[2];
            sgat[(r0+8) * 5 + 2*tq + 1]  = Da[3] + Db[3] + Dc[3];
            sgat[(r0+16) * 5 + 2*tq]     = Ea[0] + Eb[0] + Ec[0];
            sgat[(r0+16) * 5 + 2*tq + 1] = Ea[1] + Eb[1] + Ec[1];
            sgat[(r0+24) * 5 + 2*tq]     = Ea[2] + Eb[2] + Ec[2];
            sgat[(r0+24) * 5 + 2*tq + 1] = Ea[3] + Eb[3] + Ec[3];
        }
        __syncthreads();

        {
            float vi = sgat[j * 5 + cb]          + bias4[0] + wx04[0] * xv.x + wx14[0] * xv.y;
            float vf = sgat[(j + 128) * 5 + cb]  + bias4[1] + wx04[1] * xv.x + wx14[1] * xv.y;
            float vg = sgat[(j + 256) * 5 + cb]  + bias4[2] + wx04[2] * xv.x + wx14[2] * xv.y;
            float vo = sgat[(j + 384) * 5 + cb]  + bias4[3] + wx04[3] * xv.x + wx14[3] * xv.y;
            float i_ = mysig(vi), f_ = mysig(vf), gg = mytanh(vg), o_ = mysig(vo);
            cc = fmaf(f_, cc, i_ * gg);
            float h = o_ * mytanh(cc);
            size_t oi = ((size_t)(bg0 + cb) * TT + t) * 256 + dir * 128 + j;
            __nv_bfloat16 hh = __float2bfloat16(h);
            __nv_bfloat16 ll = __float2bfloat16(h - __bfloat162float(hh));
            y1h[oi] = hh;
            y1l[oi] = ll;
            *(__nv_bfloat16*)(sm + L1_BHI + bko) = hh;
            *(__nv_bfloat16*)(sm + L1_BLO + bko) = ll;
        }
        __syncthreads();
    }
}

// ============ weight split prep ============
__global__ void wsplit_kernel(const float* __restrict__ W,
    __nv_bfloat16* __restrict__ wh, __nv_bfloat16* __restrict__ wl, int n)
{
    int i = blockIdx.x * 256 + threadIdx.x;
    if (i < n) {
        float v = W[i];
        __nv_bfloat16 h = __float2bfloat16(v);
        wh[i] = h;
        wl[i] = __float2bfloat16(v - __bfloat162float(h));
    }
}

// ============ generalized bf16 3-term HMMA GEMM + bias, ldmatrix frags =====
#define GPAD 40
__global__ __launch_bounds__(256) void gemm_hmma(
    const __nv_bfloat16* __restrict__ Ah, const __nv_bfloat16* __restrict__ Al,
    const __nv_bfloat16* __restrict__ Bh, const __nv_bfloat16* __restrict__ Bl,
    const float* __restrict__ b1, const float* __restrict__ b2,
    float* __restrict__ C, int N, int K)
{
    __shared__ __nv_bfloat16 sAh[128][GPAD], sAl[128][GPAD];
    __shared__ __nv_bfloat16 sBh[128][GPAD], sBl[128][GPAD];
    const int m0 = blockIdx.y * 128, n0 = blockIdx.x * 128;
    const int tid = threadIdx.x, wid = tid >> 5, lane = tid & 31;
    const int wm = wid & 3, wn = wid >> 2;
    const int g = lane >> 2, tq = lane & 3;
    const int seg = lane >> 3, rr = lane & 7;

    float D[2][8][4];
    #pragma unroll
    for (int mt = 0; mt < 2; mt++)
        #pragma unroll
        for (int nt = 0; nt < 8; nt++)
            #pragma unroll
            for (int q = 0; q < 4; q++) D[mt][nt][q] = 0.0f;

    for (int kb = 0; kb < K; kb += 32) {
        #pragma unroll
        for (int i = 0; i < 2; i++) {
            int c = tid * 2 + i;
            int row = c >> 2, q = c & 3;
            *(uint4*)&sAh[row][q * 8] = *(const uint4*)(Ah + (size_t)(m0 + row) * K + kb + q * 8);
            *(uint4*)&sAl[row][q * 8] = *(const uint4*)(Al + (size_t)(m0 + row) * K + kb + q * 8);
            *(uint4*)&sBh[row][q * 8] = *(const uint4*)(Bh + (size_t)(n0 + row) * K + kb + q * 8);
            *(uint4*)&sBl[row][q * 8] = *(const uint4*)(Bl + (size_t)(n0 + row) * K + kb + q * 8);
        }
        __syncthreads();
        #pragma unroll
        for (int kk = 0; kk < 2; kk++) {
            u32 ah[2][4], al[2][4], bh[8][2], bl[8][2];
            #pragma unroll
            for (int mt = 0; mt < 2; mt++) {
                int ar = wm * 32 + mt * 16 + (seg & 1) * 8 + rr;
                int ac = kk * 16 + (seg >> 1) * 8;
                ldm4(ah[mt], &sAh[ar][ac]);
                ldm4(al[mt], &sAl[ar][ac]);
            }
            #pragma unroll
            for (int p = 0; p < 4; p++) {
                int br = wn * 64 + p * 16 + (seg >> 1) * 8 + rr;
                int bc = kk * 16 + (seg & 1) * 8;
                ldm4(&bh[2 * p][0], &sBh[br][bc]);
                ldm4(&bl[2 * p][0], &sBl[br][bc]);
            }
            #pragma unroll
            for (int mt = 0; mt < 2; mt++)
                #pragma unroll
                for (int nt = 0; nt < 8; nt++) {
                    mma_bf16(D[mt][nt], ah[mt], bh[nt]);
                    mma_bf16(D[mt][nt], al[mt], bh[nt]);
                    mma_bf16(D[mt][nt], ah[mt], bl[nt]);
                }
        }
        __syncthreads();
    }
    #pragma unroll
    for (int mt = 0; mt < 2; mt++) {
        size_t r0 = (size_t)(m0 + wm * 32 + mt * 16 + g);
        size_t r1 = r0 + 8;
        #pragma unroll
        for (int nt = 0; nt < 8; nt++) {
            int c0 = n0 + wn * 64 + nt * 8 + 2 * tq;
            float bA = b1[c0] + b2[c0];
            float bB = b1[c0 + 1] + b2[c0 + 1];
            C[r0 * N + c0]     = D[mt][nt][0] + bA;
            C[r0 * N + c0 + 1] = D[mt][nt][1] + bB;
            C[r1 * N + c0]     = D[mt][nt][2] + bA;
            C[r1 * N + c0 + 1] = D[mt][nt][3] + bB;
        }
    }
}

// ============ Layer 2: H=64, CTA per chain; emits bf16 hi/lo ============
#define L2_SMEM_BYTES (32 * 256 * 8 + 64 * 4 + 256 * 4)
__global__ __launch_bounds__(256, 1) void lstm2_kernel(
    const float* __restrict__ xg, const float* __restrict__ Whh,
    __nv_bfloat16* __restrict__ y2h, __nv_bfloat16* __restrict__ y2l)
{
    extern __shared__ char smraw[];
    ull*   sW2 = (ull*)smraw;
    float* sh  = (float*)(smraw + 32 * 256 * 8);
    float* sg  = sh + 64;
    const int r = threadIdx.x;
    const int b = blockIdx.x >> 1, dir = blockIdx.x & 1;
    const int gate = r >> 6, j = r & 63;
    const float* WhhD = Whh + (size_t)dir * 256 * 64;

    for (int i = r; i < 32 * 256; i += 256) {
        int kp = i >> 8, rr = i & 255;
        sW2[i] = *(const ull*)(WhhD + rr * 64 + 2 * kp);
    }
    if (r < 64) sh[r] = 0.0f;
    float cc = 0.0f;
    __syncthreads();

    const float* xgb = xg + (size_t)b * TT * 512 + dir * 256 + r;
    const int t0 = dir ? (TT - 1) : 0;
    float xt = __ldg(xgb + (size_t)t0 * 512);

    for (int s = 0; s < TT; s++) {
        const int t = dir ? (TT - 1 - s) : s;
        float xnext = 0.0f;
        if (s + 1 < TT) {
            const int tn = dir ? (TT - 2 - s) : (s + 1);
            xnext = __ldg(xgb + (size_t)tn * 512);
        }
        ull accA = 0ull, accB = 0ull;
        #pragma unroll
        for (int kp = 0; kp < 32; kp += 2) {
            fma2(accA, sW2[kp * 256 + r],       *(const ull*)(sh + 2 * kp));
            fma2(accB, sW2[(kp + 1) * 256 + r], *(const ull*)(sh + 2 * kp + 2));
        }
        float alo, ahi, blo, bhi;
        upk(accA, alo, ahi); upk(accB, blo, bhi);
        float v = xt + (alo + ahi) + (blo + bhi);
        sg[r] = (gate == 2) ? mytanh(v) : mysig(v);
        __syncthreads();
        if (r < 64) {
            float i_ = sg[j], f_ = sg[j+64], gg = sg[j+128], o_ = sg[j+192];
            cc = fmaf(f_, cc, i_ * gg);
            float h = o_ * mytanh(cc);
            sh[j] = h;
            size_t oi = ((size_t)b * TT + t) * 128 + dir * 64 + j;
            __nv_bfloat16 hh = __float2bfloat16(h);
            y2h[oi] = hh;
            y2l[oi] = __float2bfloat16(h - __bfloat162float(hh));
        }
        __syncthreads();
        xt = xnext;
    }
}

// ============ Layer 3 + mean: warp per chain ============
__global__ __launch_bounds__(256, 1) void lstm3_kernel(
    const float* __restrict__ xg, const float* __restrict__ Whh,
    float* __restrict__ s3)
{
    __shared__ float shh[8][16];
    const int tid = threadIdx.x, wid = tid >> 5, lane = tid & 31;
    const int pg = blockIdx.x * 8 + wid;
    const int b = pg >> 1, dir = pg & 1;
    const int r0 = lane, r1 = lane + 32;
    const float* WhhD = Whh + (size_t)dir * 64 * 16;
    float* shp = shh[wid];

    ull w0[8], w1[8];
    #pragma unroll
    for (int kp = 0; kp < 8; kp++) {
        w0[kp] = *(const ull*)(WhhD + r0 * 16 + 2 * kp);
        w1[kp] = *(const ull*)(WhhD + r1 * 16 + 2 * kp);
    }
    if (lane < 16) shp[lane] = 0.0f;
    float cc = 0.0f, sum = 0.0f;
    __syncwarp();

    const float* xgb = xg + (size_t)b * TT * 128 + dir * 64;
    const int t0 = dir ? (TT - 1) : 0;
    float xt0 = __ldg(xgb + (size_t)t0 * 128 + r0);
    float xt1 = __ldg(xgb + (size_t)t0 * 128 + r1);

    for (int s = 0; s < TT; s++) {
        float xn0 = 0.0f, xn1 = 0.0f;
        if (s + 1 < TT) {
            const int tn = dir ? (TT - 2 - s) : (s + 1);
            xn0 = __ldg(xgb + (size_t)tn * 128 + r0);
            xn1 = __ldg(xgb + (size_t)tn * 128 + r1);
        }
        ull a0 = 0ull, a1 = 0ull;
        #pragma unroll
        for (int kp = 0; kp < 8; kp++) {
            ull hb = *(const ull*)(shp + 2 * kp);
            fma2(a0, w0[kp], hb);
            fma2(a1, w1[kp], hb);
        }
        float l0, h0, l1, h1;
        upk(a0, l0, h0); upk(a1, l1, h1);
        float v0 = xt0 + l0 + h0, v1 = xt1 + l1 + h1;
        float g0 = mysig(v0);
        float g1 = (lane < 16) ? mytanh(v1) : mysig(v1);
        float f_ = __shfl_down_sync(0xffffffffu, g0, 16);
        float o_ = __shfl_down_sync(0xffffffffu, g1, 16);
        if (lane < 16) {
            cc = fmaf(f_, cc, g0 * g1);
            float h = o_ * mytanh(cc);
            shp[lane] = h;
            sum += h;
        }
        __syncwarp();
        xt0 = xn0; xt1 = xn1;
    }
    if (lane < 16) s3[b * 32 + dir * 16 + lane] = sum * (1.0f / TT);
}

// ============ MLP head ============
__global__ void mlp_kernel(
    const float* __restrict__ s3,
    const float* __restrict__ hW1, const float* __restrict__ hb1,
    const float* __restrict__ hW2, const float* __restrict__ hb2,
    const float* __restrict__ hW3, const float* __restrict__ hb3,
    float* __restrict__ out)
{
    int b = blockIdx.x * blockDim.x + threadIdx.x;
    if (b >= BB) return;
    float s[32];
    #pragma unroll
    for (int k = 0; k < 32; k++) s[k] = s3[b * 32 + k];
    float h1[64];
    for (int o = 0; o < 64; o++) {
        float a = hb1[o];
        #pragma unroll
        for (int k = 0; k < 32; k++) a = fmaf(s[k], hW1[o * 32 + k], a);
        h1[o] = fmaxf(a, 0.0f);
    }
    float h2[16];
    for (int o = 0; o < 16; o++) {
        float a = hb2[o];
        #pragma unroll
        for (int k = 0; k < 64; k++) a = fmaf(h1[k], hW2[o * 64 + k], a);
        h2[o] = fmaxf(a, 0.0f);
    }
    for (int o = 0; o < 20; o++) {
        float a = hb3[o];
        #pragma unroll
        for (int k = 0; k < 16; k++) a = fmaf(h2[k], hW3[o * 16 + k], a);
        out[b * 20 + o] = a;
    }
}

extern "C" void kernel_launch(void* const* d_in, const int* in_sizes, int n_in,
                              void* d_out, int out_size)
{
    const float* x    = (const float*)d_in[0];
    const float* Wih1 = (const float*)d_in[1];
    const float* Whh1 = (const float*)d_in[2];
    const float* bih1 = (const float*)d_in[3];
    const float* bhh1 = (const float*)d_in[4];
    const float* Wih2 = (const float*)d_in[5];
    const float* Whh2 = (const float*)d_in[6];
    const float* bih2 = (const float*)d_in[7];
    const float* bhh2 = (const float*)d_in[8];
    const float* Wih3 = (const float*)d_in[9];
    const float* Whh3 = (const float*)d_in[10];
    const float* bih3 = (const float*)d_in[11];
    const float* bhh3 = (const float*)d_in[12];
    const float* hW1  = (const float*)d_in[13];
    const float* hb1  = (const float*)d_in[14];
    const float* hW2  = (const float*)d_in[15];
    const float* hb2  = (const float*)d_in[16];
    const float* hW3  = (const float*)d_in[17];
    const float* hb3  = (const float*)d_in[18];
    float* out = (float*)d_out;

    __nv_bfloat16 *y1h, *y1l, *w2h, *w2l, *w3h, *w3l, *y2h, *y2l;
    float *xg2, *xg3, *s3;
    cudaGetSymbolAddress((void**)&y1h, g_y1h);
    cudaGetSymbolAddress((void**)&y1l, g_y1l);
    cudaGetSymbolAddress((void**)&w2h, g_w2h);
    cudaGetSymbolAddress((void**)&w2l, g_w2l);
    cudaGetSymbolAddress((void**)&w3h, g_w3h);
    cudaGetSymbolAddress((void**)&w3l, g_w3l);
    cudaGetSymbolAddress((void**)&y2h, g_y2h);
    cudaGetSymbolAddress((void**)&y2l, g_y2l);
    cudaGetSymbolAddress((void**)&xg2, g_xg2);
    cudaGetSymbolAddress((void**)&xg3, g_xg3);
    cudaGetSymbolAddress((void**)&s3,  g_sum3);

    static bool attr_set = false;
    if (!attr_set) {
        cudaFuncSetAttribute(lstm1_mma,
            cudaFuncAttributeMaxDynamicSharedMemorySize, L1_SMEM);
        cudaFuncSetAttribute(lstm2_kernel,
            cudaFuncAttributeMaxDynamicSharedMemorySize, L2_SMEM_BYTES);
        attr_set = true;
    }

    const int M = BB * TT;
    wsplit_kernel<<<512, 256>>>(Wih2, w2h, w2l, 512 * 256);
    wsplit_kernel<<<64, 256>>>(Wih3, w3h, w3l, 128 * 128);
    lstm1_mma<<<dim3(64, 2), 512, L1_SMEM>>>(x, Wih1, Whh1, bih1, bhh1, y1h, y1l);
    gemm_hmma<<<dim3(4, M / 128), 256>>>(y1h, y1l, w2h, w2l, bih2, bhh2, xg2, 512, 256);
    lstm2_kernel<<<512, 256, L2_SMEM_BYTES>>>(xg2, Whh2, y2h, y2l);
    gemm_hmma<<<dim3(1, M / 128), 256>>>(y2h, y2l, w3h, w3l, bih3, bhh3, xg3, 128, 128);
    lstm3_kernel<<<64, 256>>>(xg3, Whh3, s3);
    mlp_kernel<<<1, 256>>>(s3, hW1, hb1, hW2, hb2, hW3, hb3, out);
}

// round 13
// speedup vs baseline: 1.2676x; 1.2676x over previous
#include <cuda_runtime.h>
#include <cuda_bf16.h>
#include <cuda_fp16.h>
#include <math.h>

#define BB 256
#define TT 2048
typedef unsigned long long ull;
typedef unsigned int u32;

__device__ __nv_bfloat16 g_y1h[(size_t)BB * TT * 256];
__device__ __nv_bfloat16 g_y1l[(size_t)BB * TT * 256];
__device__ __nv_bfloat16 g_w2h[512 * 256];
__device__ __nv_bfloat16 g_w2l[512 * 256];
__device__ __nv_bfloat16 g_w3h[128 * 128];
__device__ __nv_bfloat16 g_w3l[128 * 128];
__device__ __nv_bfloat16 g_y2h[(size_t)BB * TT * 128];
__device__ __nv_bfloat16 g_y2l[(size_t)BB * TT * 128];
__device__ float g_xg2[(size_t)BB * TT * 512];
__device__ float g_xg3[(size_t)BB * TT * 128];
__device__ float g_sum3[BB * 32];

__device__ __forceinline__ float mysig(float v){ return __fdividef(1.0f, 1.0f + __expf(-v)); }
__device__ __forceinline__ float mytanh(float v){
    float e = __expf(2.0f * v);
    return 1.0f - 2.0f * __fdividef(1.0f, 1.0f + e);
}
__device__ __forceinline__ void upk(ull v, float& lo, float& hi){
    asm("mov.b64 {%0, %1}, %2;" : "=f"(lo), "=f"(hi) : "l"(v));
}
__device__ __forceinline__ void fma2(ull& d, ull a, ull b){
    asm("fma.rn.f32x2 %0, %1, %2, %0;" : "+l"(d) : "l"(a), "l"(b));
}
__device__ __forceinline__ void mma_bf16(float* d, const u32* a, const u32* b){
    asm volatile("mma.sync.aligned.m16n8k16.row.col.f32.bf16.bf16.f32 "
        "{%0,%1,%2,%3}, {%4,%5,%6,%7}, {%8,%9}, {%0,%1,%2,%3};"
        : "+f"(d[0]), "+f"(d[1]), "+f"(d[2]), "+f"(d[3])
        : "r"(a[0]), "r"(a[1]), "r"(a[2]), "r"(a[3]), "r"(b[0]), "r"(b[1]));
}
__device__ __forceinline__ void mma_f16(float* d, const u32* a, const u32* b){
    asm volatile("mma.sync.aligned.m16n8k16.row.col.f32.f16.f16.f32 "
        "{%0,%1,%2,%3}, {%4,%5,%6,%7}, {%8,%9}, {%0,%1,%2,%3};"
        : "+f"(d[0]), "+f"(d[1]), "+f"(d[2]), "+f"(d[3])
        : "r"(a[0]), "r"(a[1]), "r"(a[2]), "r"(a[3]), "r"(b[0]), "r"(b[1]));
}
__device__ __forceinline__ u32 hi2(float a, float b){
    return (u32)__bfloat16_as_ushort(__float2bfloat16(a))
         | ((u32)__bfloat16_as_ushort(__float2bfloat16(b)) << 16);
}
__device__ __forceinline__ u32 h2u(float a, float b){
    __half2 t = __floats2half2_rn(a, b);
    return *(u32*)&t;
}

// ============ Layer 1 via fp16 single-term mma.sync ============
// CTA = 4 batches x 1 dir, grid (64,2), 512 thr, warp w owns m-tiles 2w,2w+1.
// W fp16 fragments fully register-resident; h fp16 in B-fragment-permuted
// smem plane; gates fp32 in smem [512][4].
#define L1_BHI  0          // fp16 B plane: [8 ks][32 l][2 u32] = 2KB
#define L1_GAT  2048       // float[512][4] = 8KB
#define L1_SMEM 10240

__global__ __launch_bounds__(512, 1) void lstm1_mma(
    const float* __restrict__ x, const float* __restrict__ Wih,
    const float* __restrict__ Whh, const float* __restrict__ bih,
    const float* __restrict__ bhh,
    __nv_bfloat16* __restrict__ y1h, __nv_bfloat16* __restrict__ y1l)
{
    extern __shared__ char sm[];
    float* sgat = (float*)(sm + L1_GAT);

    const int tid = threadIdx.x, w = tid >> 5, l = tid & 31;
    const int g = l >> 2, tq = l & 3;
    const int dir = blockIdx.y, bg0 = blockIdx.x * 4;
    const float* WD = Whh + (size_t)dir * 512 * 128;

    // A fragments (fp16) in registers: 2 m-tiles x 8 k-steps x 4 u32
    u32 Ah[2][8][4];
    #pragma unroll
    for (int mt = 0; mt < 2; mt++)
        #pragma unroll
        for (int ks = 0; ks < 8; ks++) {
            int R = 32 * w + 16 * mt + g, C = 16 * ks + 2 * tq;
            const float* p0 = WD + (size_t)R * 128 + C;
            const float* p1 = WD + (size_t)(R + 8) * 128 + C;
            Ah[mt][ks][0] = h2u(p0[0], p0[1]);
            Ah[mt][ks][1] = h2u(p1[0], p1[1]);
            Ah[mt][ks][2] = h2u(p0[8], p0[9]);
            Ah[mt][ks][3] = h2u(p1[8], p1[9]);
        }
    // zero B plane
    if (tid < 512) ((u32*)(sm + L1_BHI))[tid] = 0;

    const int cb = tid >> 7, j = tid & 127;
    float bias4[4], wx04[4], wx14[4];
    #pragma unroll
    for (int q = 0; q < 4; q++) {
        int rq = j + 128 * q;
        bias4[q] = bih[dir * 512 + rq] + bhh[dir * 512 + rq];
        wx04[q] = Wih[dir * 1024 + rq * 2];
        wx14[q] = Wih[dir * 1024 + rq * 2 + 1];
    }
    const u32 bko = (u32)(j >> 4) * 256 + (u32)(4 * cb + ((j & 7) >> 1)) * 8
                  + (u32)((j >> 3) & 1) * 4 + (u32)(j & 1) * 2;
    float cc = 0.0f;
    __syncthreads();

    for (int s = 0; s < TT; s++) {
        const int t = dir ? (TT - 1 - s) : s;
        float2 xv = __ldg((const float2*)(x + ((size_t)(bg0 + cb) * TT + t) * 2));

        float D0[4] = {0.f, 0.f, 0.f, 0.f};
        float D1[4] = {0.f, 0.f, 0.f, 0.f};
        #pragma unroll
        for (int ks = 0; ks < 8; ks++) {
            uint2 bh = *(const uint2*)(sm + L1_BHI + ks * 256 + l * 8);
            mma_f16(D0, Ah[0][ks], &bh.x);
            mma_f16(D1, Ah[1][ks], &bh.x);
        }
        if (tq < 2) {
            int r0 = 32 * w + g;
            *(float2*)(sm + L1_GAT + r0 * 16 + tq * 8)        = make_float2(D0[0], D0[1]);
            *(float2*)(sm + L1_GAT + (r0 + 8) * 16 + tq * 8)  = make_float2(D0[2], D0[3]);
            *(float2*)(sm + L1_GAT + (r0 + 16) * 16 + tq * 8) = make_float2(D1[0], D1[1]);
            *(float2*)(sm + L1_GAT + (r0 + 24) * 16 + tq * 8) = make_float2(D1[2], D1[3]);
        }
        __syncthreads();

        {
            float vi = sgat[j * 4 + cb]          + bias4[0] + wx04[0] * xv.x + wx14[0] * xv.y;
            float vf = sgat[(j + 128) * 4 + cb]  + bias4[1] + wx04[1] * xv.x + wx14[1] * xv.y;
            float vg = sgat[(j + 256) * 4 + cb]  + bias4[2] + wx04[2] * xv.x + wx14[2] * xv.y;
            float vo = sgat[(j + 384) * 4 + cb]  + bias4[3] + wx04[3] * xv.x + wx14[3] * xv.y;
            float i_ = mysig(vi), f_ = mysig(vf), gg = mytanh(vg), o_ = mysig(vo);
            cc = fmaf(f_, cc, i_ * gg);
            float h = o_ * mytanh(cc);
            size_t oi = ((size_t)(bg0 + cb) * TT + t) * 256 + dir * 128 + j;
            __nv_bfloat16 hh = __float2bfloat16(h);
            y1h[oi] = hh;
            y1l[oi] = __float2bfloat16(h - __bfloat162float(hh));
            *(__half*)(sm + L1_BHI + bko) = __float2half_rn(h);
        }
        __syncthreads();
    }
}

// ============ weight split prep ============
__global__ void wsplit_kernel(const float* __restrict__ W,
    __nv_bfloat16* __restrict__ wh, __nv_bfloat16* __restrict__ wl, int n)
{
    int i = blockIdx.x * 256 + threadIdx.x;
    if (i < n) {
        float v = W[i];
        __nv_bfloat16 h = __float2bfloat16(v);
        wh[i] = h;
        wl[i] = __float2bfloat16(v - __bfloat162float(h));
    }
}

// ============ bf16 3-term HMMA GEMM + bias (R9-validated scalar frags) =====
#define GPAD 40
__global__ __launch_bounds__(256) void gemm_hmma(
    const __nv_bfloat16* __restrict__ Ah, const __nv_bfloat16* __restrict__ Al,
    const __nv_bfloat16* __restrict__ Bh, const __nv_bfloat16* __restrict__ Bl,
    const float* __restrict__ b1, const float* __restrict__ b2,
    float* __restrict__ C, int N, int K)
{
    __shared__ __nv_bfloat16 sAh[128][GPAD], sAl[128][GPAD];
    __shared__ __nv_bfloat16 sBh[128][GPAD], sBl[128][GPAD];
    const int m0 = blockIdx.y * 128, n0 = blockIdx.x * 128;
    const int tid = threadIdx.x, wid = tid >> 5, lane = tid & 31;
    const int wm = wid & 3, wn = wid >> 2;
    const int g = lane >> 2, tq = lane & 3;

    float D[2][8][4];
    #pragma unroll
    for (int mt = 0; mt < 2; mt++)
        #pragma unroll
        for (int nt = 0; nt < 8; nt++)
            #pragma unroll
            for (int q = 0; q < 4; q++) D[mt][nt][q] = 0.0f;

    for (int kb = 0; kb < K; kb += 32) {
        #pragma unroll
        for (int i = 0; i < 2; i++) {
            int c = tid * 2 + i;
            int row = c >> 2, q = c & 3;
            *(uint4*)&sAh[row][q * 8] = *(const uint4*)(Ah + (size_t)(m0 + row) * K + kb + q * 8);
            *(uint4*)&sAl[row][q * 8] = *(const uint4*)(Al + (size_t)(m0 + row) * K + kb + q * 8);
            *(uint4*)&sBh[row][q * 8] = *(const uint4*)(Bh + (size_t)(n0 + row) * K + kb + q * 8);
            *(uint4*)&sBl[row][q * 8] = *(const uint4*)(Bl + (size_t)(n0 + row) * K + kb + q * 8);
        }
        __syncthreads();
        #pragma unroll
        for (int kk = 0; kk < 2; kk++) {
            u32 ah[2][4], al[2][4], bh[8][2], bl[8][2];
            #pragma unroll
            for (int mt = 0; mt < 2; mt++) {
                int r0 = wm * 32 + mt * 16 + g;
                int kc = kk * 16 + 2 * tq;
                ah[mt][0] = *(const u32*)&sAh[r0][kc];
                ah[mt][1] = *(const u32*)&sAh[r0 + 8][kc];
                ah[mt][2] = *(const u32*)&sAh[r0][kc + 8];
                ah[mt][3] = *(const u32*)&sAh[r0 + 8][kc + 8];
                al[mt][0] = *(const u32*)&sAl[r0][kc];
                al[mt][1] = *(const u32*)&sAl[r0 + 8][kc];
                al[mt][2] = *(const u32*)&sAl[r0][kc + 8];
                al[mt][3] = *(const u32*)&sAl[r0 + 8][kc + 8];
            }
            #pragma unroll
            for (int nt = 0; nt < 8; nt++) {
                int n_ = wn * 64 + nt * 8 + g;
                int kc = kk * 16 + 2 * tq;
                bh[nt][0] = *(const u32*)&sBh[n_][kc];
                bh[nt][1] = *(const u32*)&sBh[n_][kc + 8];
                bl[nt][0] = *(const u32*)&sBl[n_][kc];
                bl[nt][1] = *(const u32*)&sBl[n_][kc + 8];
            }
            #pragma unroll
            for (int mt = 0; mt < 2; mt++)
                #pragma unroll
                for (int nt = 0; nt < 8; nt++) {
                    mma_bf16(D[mt][nt], ah[mt], bh[nt]);
                    mma_bf16(D[mt][nt], al[mt], bh[nt]);
                    mma_bf16(D[mt][nt], ah[mt], bl[nt]);
                }
        }
        __syncthreads();
    }
    #pragma unroll
    for (int mt = 0; mt < 2; mt++) {
        size_t r0 = (size_t)(m0 + wm * 32 + mt * 16 + g);
        size_t r1 = r0 + 8;
        #pragma unroll
        for (int nt = 0; nt < 8; nt++) {
            int c0 = n0 + wn * 64 + nt * 8 + 2 * tq;
            float bA = b1[c0] + b2[c0];
            float bB = b1[c0 + 1] + b2[c0 + 1];
            C[r0 * N + c0]     = D[mt][nt][0] + bA;
            C[r0 * N + c0 + 1] = D[mt][nt][1] + bB;
            C[r1 * N + c0]     = D[mt][nt][2] + bA;
            C[r1 * N + c0 + 1] = D[mt][nt][3] + bB;
        }
    }
}

// ============ Layer 2: H=64, CTA per chain; emits bf16 hi/lo ============
#define L2_SMEM_BYTES (32 * 256 * 8 + 64 * 4 + 256 * 4)
__global__ __launch_bounds__(256, 1) void lstm2_kernel(
    const float* __restrict__ xg, const float* __restrict__ Whh,
    __nv_bfloat16* __restrict__ y2h, __nv_bfloat16* __restrict__ y2l)
{
    extern __shared__ char smraw[];
    ull*   sW2 = (ull*)smraw;
    float* sh  = (float*)(smraw + 32 * 256 * 8);
    float* sg  = sh + 64;
    const int r = threadIdx.x;
    const int b = blockIdx.x >> 1, dir = blockIdx.x & 1;
    const int gate = r >> 6, j = r & 63;
    const float* WhhD = Whh + (size_t)dir * 256 * 64;

    for (int i = r; i < 32 * 256; i += 256) {
        int kp = i >> 8, rr = i & 255;
        sW2[i] = *(const ull*)(WhhD + rr * 64 + 2 * kp);
    }
    if (r < 64) sh[r] = 0.0f;
    float cc = 0.0f;
    __syncthreads();

    const float* xgb = xg + (size_t)b * TT * 512 + dir * 256 + r;
    const int t0 = dir ? (TT - 1) : 0;
    float xt = __ldg(xgb + (size_t)t0 * 512);

    for (int s = 0; s < TT; s++) {
        const int t = dir ? (TT - 1 - s) : s;
        float xnext = 0.0f;
        if (s + 1 < TT) {
            const int tn = dir ? (TT - 2 - s) : (s + 1);
            xnext = __ldg(xgb + (size_t)tn * 512);
        }
        ull accA = 0ull, accB = 0ull;
        #pragma unroll
        for (int kp = 0; kp < 32; kp += 2) {
            fma2(accA, sW2[kp * 256 + r],       *(const ull*)(sh + 2 * kp));
            fma2(accB, sW2[(kp + 1) * 256 + r], *(const ull*)(sh + 2 * kp + 2));
        }
        float alo, ahi, blo, bhi;
        upk(accA, alo, ahi); upk(accB, blo, bhi);
        float v = xt + (alo + ahi) + (blo + bhi);
        sg[r] = (gate == 2) ? mytanh(v) : mysig(v);
        __syncthreads();
        if (r < 64) {
            float i_ = sg[j], f_ = sg[j+64], gg = sg[j+128], o_ = sg[j+192];
            cc = fmaf(f_, cc, i_ * gg);
            float h = o_ * mytanh(cc);
            sh[j] = h;
            size_t oi = ((size_t)b * TT + t) * 128 + dir * 64 + j;
            __nv_bfloat16 hh = __float2bfloat16(h);
            y2h[oi] = hh;
            y2l[oi] = __float2bfloat16(h - __bfloat162float(hh));
        }
        __syncthreads();
        xt = xnext;
    }
}

// ============ Layer 3 + mean: warp per chain ============
__global__ __launch_bounds__(256, 1) void lstm3_kernel(
    const float* __restrict__ xg, const float* __restrict__ Whh,
    float* __restrict__ s3)
{
    __shared__ float shh[8][16];
    const int tid = threadIdx.x, wid = tid >> 5, lane = tid & 31;
    const int pg = blockIdx.x * 8 + wid;
    const int b = pg >> 1, dir = pg & 1;
    const int r0 = lane, r1 = lane + 32;
    const float* WhhD = Whh + (size_t)dir * 64 * 16;
    float* shp = shh[wid];

    ull w0[8], w1[8];
    #pragma unroll
    for (int kp = 0; kp < 8; kp++) {
        w0[kp] = *(const ull*)(WhhD + r0 * 16 + 2 * kp);
        w1[kp] = *(const ull*)(WhhD + r1 * 16 + 2 * kp);
    }
    if (lane < 16) shp[lane] = 0.0f;
    float cc = 0.0f, sum = 0.0f;
    __syncwarp();

    const float* xgb = xg + (size_t)b * TT * 128 + dir * 64;
    const int t0 = dir ? (TT - 1) : 0;
    float xt0 = __ldg(xgb + (size_t)t0 * 128 + r0);
    float xt1 = __ldg(xgb + (size_t)t0 * 128 + r1);

    for (int s = 0; s < TT; s++) {
        float xn0 = 0.0f, xn1 = 0.0f;
        if (s + 1 < TT) {
            const int tn = dir ? (TT - 2 - s) : (s + 1);
            xn0 = __ldg(xgb + (size_t)tn * 128 + r0);
            xn1 = __ldg(xgb + (size_t)tn * 128 + r1);
        }
        ull a0 = 0ull, a1 = 0ull;
        #pragma unroll
        for (int kp = 0; kp < 8; kp++) {
            ull hb = *(const ull*)(shp + 2 * kp);
            fma2(a0, w0[kp], hb);
            fma2(a1, w1[kp], hb);
        }
        float l0, h0, l1, h1;
        upk(a0, l0, h0); upk(a1, l1, h1);
        float v0 = xt0 + l0 + h0, v1 = xt1 + l1 + h1;
        float g0 = mysig(v0);
        float g1 = (lane < 16) ? mytanh(v1) : mysig(v1);
        float f_ = __shfl_down_sync(0xffffffffu, g0, 16);
        float o_ = __shfl_down_sync(0xffffffffu, g1, 16);
        if (lane < 16) {
            cc = fmaf(f_, cc, g0 * g1);
            float h = o_ * mytanh(cc);
            shp[lane] = h;
            sum += h;
        }
        __syncwarp();
        xt0 = xn0; xt1 = xn1;
    }
    if (lane < 16) s3[b * 32 + dir * 16 + lane] = sum * (1.0f / TT);
}

// ============ MLP head ============
__global__ void mlp_kernel(
    const float* __restrict__ s3,
    const float* __restrict__ hW1, const float* __restrict__ hb1,
    const float* __restrict__ hW2, const float* __restrict__ hb2,
    const float* __restrict__ hW3, const float* __restrict__ hb3,
    float* __restrict__ out)
{
    int b = blockIdx.x * blockDim.x + threadIdx.x;
    if (b >= BB) return;
    float s[32];
    #pragma unroll
    for (int k = 0; k < 32; k++) s[k] = s3[b * 32 + k];
    float h1[64];
    for (int o = 0; o < 64; o++) {
        float a = hb1[o];
        #pragma unroll
        for (int k = 0; k < 32; k++) a = fmaf(s[k], hW1[o * 32 + k], a);
        h1[o] = fmaxf(a, 0.0f);
    }
    float h2[16];
    for (int o = 0; o < 16; o++) {
        float a = hb2[o];
        #pragma unroll
        for (int k = 0; k < 64; k++) a = fmaf(h1[k], hW2[o * 64 + k], a);
        h2[o] = fmaxf(a, 0.0f);
    }
    for (int o = 0; o < 20; o++) {
        float a = hb3[o];
        #pragma unroll
        for (int k = 0; k < 16; k++) a = fmaf(h2[k], hW3[o * 16 + k], a);
        out[b * 20 + o] = a;
    }
}

extern "C" void kernel_launch(void* const* d_in, const int* in_sizes, int n_in,
                              void* d_out, int out_size)
{
    const float* x    = (const float*)d_in[0];
    const float* Wih1 = (const float*)d_in[1];
    const float* Whh1 = (const float*)d_in[2];
    const float* bih1 = (const float*)d_in[3];
    const float* bhh1 = (const float*)d_in[4];
    const float* Wih2 = (const float*)d_in[5];
    const float* Whh2 = (const float*)d_in[6];
    const float* bih2 = (const float*)d_in[7];
    const float* bhh2 = (const float*)d_in[8];
    const float* Wih3 = (const float*)d_in[9];
    const float* Whh3 = (const float*)d_in[10];
    const float* bih3 = (const float*)d_in[11];
    const float* bhh3 = (const float*)d_in[12];
    const float* hW1  = (const float*)d_in[13];
    const float* hb1  = (const float*)d_in[14];
    const float* hW2  = (const float*)d_in[15];
    const float* hb2  = (const float*)d_in[16];
    const float* hW3  = (const float*)d_in[17];
    const float* hb3  = (const float*)d_in[18];
    float* out = (float*)d_out;

    __nv_bfloat16 *y1h, *y1l, *w2h, *w2l, *w3h, *w3l, *y2h, *y2l;
    float *xg2, *xg3, *s3;
    cudaGetSymbolAddress((void**)&y1h, g_y1h);
    cudaGetSymbolAddress((void**)&y1l, g_y1l);
    cudaGetSymbolAddress((void**)&w2h, g_w2h);
    cudaGetSymbolAddress((void**)&w2l, g_w2l);
    cudaGetSymbolAddress((void**)&w3h, g_w3h);
    cudaGetSymbolAddress((void**)&w3l, g_w3l);
    cudaGetSymbolAddress((void**)&y2h, g_y2h);
    cudaGetSymbolAddress((void**)&y2l, g_y2l);
    cudaGetSymbolAddress((void**)&xg2, g_xg2);
    cudaGetSymbolAddress((void**)&xg3, g_xg3);
    cudaGetSymbolAddress((void**)&s3,  g_sum3);

    static bool attr_set = false;
    if (!attr_set) {
        cudaFuncSetAttribute(lstm1_mma,
            cudaFuncAttributeMaxDynamicSharedMemorySize, L1_SMEM);
        cudaFuncSetAttribute(lstm2_kernel,
            cudaFuncAttributeMaxDynamicSharedMemorySize, L2_SMEM_BYTES);
        attr_set = true;
    }

    const int M = BB * TT;
    wsplit_kernel<<<512, 256>>>(Wih2, w2h, w2l, 512 * 256);
    wsplit_kernel<<<64, 256>>>(Wih3, w3h, w3l, 128 * 128);
    lstm1_mma<<<dim3(64, 2), 512, L1_SMEM>>>(x, Wih1, Whh1, bih1, bhh1, y1h, y1l);
    gemm_hmma<<<dim3(4, M / 128), 256>>>(y1h, y1l, w2h, w2l, bih2, bhh2, xg2, 512, 256);
    lstm2_kernel<<<512, 256, L2_SMEM_BYTES>>>(xg2, Whh2, y2h, y2l);
    gemm_hmma<<<dim3(1, M / 128), 256>>>(y2h, y2l, w3h, w3l, bih3, bhh3, xg3, 128, 128);
    lstm3_kernel<<<64, 256>>>(xg3, Whh3, s3);
    mlp_kernel<<<1, 256>>>(s3, hW1, hb1, hW2, hb2, hW3, hb3, out);
}

// round 14
// speedup vs baseline: 1.4473x; 1.1418x over previous
#include <cuda_runtime.h>
#include <cuda_bf16.h>
#include <cuda_fp16.h>
#include <math.h>

#define BB 256
#define TT 2048
typedef unsigned long long ull;
typedef unsigned int u32;

__device__ __half g_y1f[(size_t)BB * TT * 256];
__device__ __half g_w2f[512 * 256];
__device__ __half g_w3f[128 * 128];
__device__ __half g_y2f[(size_t)BB * TT * 128];
__device__ float g_xg2[(size_t)BB * TT * 512];
__device__ float g_xg3[(size_t)BB * TT * 128];
__device__ float g_sum3[BB * 32];

__device__ __forceinline__ float mysig(float v){ return __fdividef(1.0f, 1.0f + __expf(-v)); }
__device__ __forceinline__ float mytanh(float v){
    float e = __expf(2.0f * v);
    return 1.0f - 2.0f * __fdividef(1.0f, 1.0f + e);
}
__device__ __forceinline__ void upk(ull v, float& lo, float& hi){
    asm("mov.b64 {%0, %1}, %2;" : "=f"(lo), "=f"(hi) : "l"(v));
}
__device__ __forceinline__ void fma2(ull& d, ull a, ull b){
    asm("fma.rn.f32x2 %0, %1, %2, %0;" : "+l"(d) : "l"(a), "l"(b));
}
__device__ __forceinline__ void mma_f16(float* d, const u32* a, const u32* b){
    asm volatile("mma.sync.aligned.m16n8k16.row.col.f32.f16.f16.f32 "
        "{%0,%1,%2,%3}, {%4,%5,%6,%7}, {%8,%9}, {%0,%1,%2,%3};"
        : "+f"(d[0]), "+f"(d[1]), "+f"(d[2]), "+f"(d[3])
        : "r"(a[0]), "r"(a[1]), "r"(a[2]), "r"(a[3]), "r"(b[0]), "r"(b[1]));
}
__device__ __forceinline__ u32 h2u(float a, float b){
    __half2 t = __floats2half2_rn(a, b);
    return *(u32*)&t;
}

// ============ Layer 1 via fp16 single-term mma.sync (R12 core) ============
#define L1_BHI  0          // fp16 B plane: [8 ks][32 l][2 u32] = 2KB
#define L1_GAT  2048       // float[512][4] = 8KB
#define L1_SMEM 10240

__global__ __launch_bounds__(512, 1) void lstm1_mma(
    const float* __restrict__ x, const float* __restrict__ Wih,
    const float* __restrict__ Whh, const float* __restrict__ bih,
    const float* __restrict__ bhh,
    __half* __restrict__ y1f)
{
    extern __shared__ char sm[];
    float* sgat = (float*)(sm + L1_GAT);

    const int tid = threadIdx.x, w = tid >> 5, l = tid & 31;
    const int g = l >> 2, tq = l & 3;
    const int dir = blockIdx.y, bg0 = blockIdx.x * 4;
    const float* WD = Whh + (size_t)dir * 512 * 128;

    u32 Ah[2][8][4];
    #pragma unroll
    for (int mt = 0; mt < 2; mt++)
        #pragma unroll
        for (int ks = 0; ks < 8; ks++) {
            int R = 32 * w + 16 * mt + g, C = 16 * ks + 2 * tq;
            const float* p0 = WD + (size_t)R * 128 + C;
            const float* p1 = WD + (size_t)(R + 8) * 128 + C;
            Ah[mt][ks][0] = h2u(p0[0], p0[1]);
            Ah[mt][ks][1] = h2u(p1[0], p1[1]);
            Ah[mt][ks][2] = h2u(p0[8], p0[9]);
            Ah[mt][ks][3] = h2u(p1[8], p1[9]);
        }
    if (tid < 512) ((u32*)(sm + L1_BHI))[tid] = 0;

    const int cb = tid >> 7, j = tid & 127;
    float bias4[4], wx04[4], wx14[4];
    #pragma unroll
    for (int q = 0; q < 4; q++) {
        int rq = j + 128 * q;
        bias4[q] = bih[dir * 512 + rq] + bhh[dir * 512 + rq];
        wx04[q] = Wih[dir * 1024 + rq * 2];
        wx14[q] = Wih[dir * 1024 + rq * 2 + 1];
    }
    const u32 bko = (u32)(j >> 4) * 256 + (u32)(4 * cb + ((j & 7) >> 1)) * 8
                  + (u32)((j >> 3) & 1) * 4 + (u32)(j & 1) * 2;
    float cc = 0.0f;
    __syncthreads();

    for (int s = 0; s < TT; s++) {
        const int t = dir ? (TT - 1 - s) : s;
        float2 xv = __ldg((const float2*)(x + ((size_t)(bg0 + cb) * TT + t) * 2));

        float D0[4] = {0.f, 0.f, 0.f, 0.f};
        float D1[4] = {0.f, 0.f, 0.f, 0.f};
        #pragma unroll
        for (int ks = 0; ks < 8; ks++) {
            uint2 bh = *(const uint2*)(sm + L1_BHI + ks * 256 + l * 8);
            mma_f16(D0, Ah[0][ks], &bh.x);
            mma_f16(D1, Ah[1][ks], &bh.x);
        }
        if (tq < 2) {
            int r0 = 32 * w + g;
            *(float2*)(sm + L1_GAT + r0 * 16 + tq * 8)        = make_float2(D0[0], D0[1]);
            *(float2*)(sm + L1_GAT + (r0 + 8) * 16 + tq * 8)  = make_float2(D0[2], D0[3]);
            *(float2*)(sm + L1_GAT + (r0 + 16) * 16 + tq * 8) = make_float2(D1[0], D1[1]);
            *(float2*)(sm + L1_GAT + (r0 + 24) * 16 + tq * 8) = make_float2(D1[2], D1[3]);
        }
        __syncthreads();

        {
            float vi = sgat[j * 4 + cb]          + bias4[0] + wx04[0] * xv.x + wx14[0] * xv.y;
            float vf = sgat[(j + 128) * 4 + cb]  + bias4[1] + wx04[1] * xv.x + wx14[1] * xv.y;
            float vg = sgat[(j + 256) * 4 + cb]  + bias4[2] + wx04[2] * xv.x + wx14[2] * xv.y;
            float vo = sgat[(j + 384) * 4 + cb]  + bias4[3] + wx04[3] * xv.x + wx14[3] * xv.y;
            float i_ = mysig(vi), f_ = mysig(vf), gg = mytanh(vg), o_ = mysig(vo);
            cc = fmaf(f_, cc, i_ * gg);
            float h = o_ * mytanh(cc);
            __half hf = __float2half_rn(h);
            y1f[((size_t)(bg0 + cb) * TT + t) * 256 + dir * 128 + j] = hf;
            *(__half*)(sm + L1_BHI + bko) = hf;
        }
        __syncthreads();
    }
}

// ============ fp32 -> fp16 weight conversion ============
__global__ void wconv_kernel(const float* __restrict__ W,
    __half* __restrict__ wf, int n)
{
    int i = blockIdx.x * 256 + threadIdx.x;
    if (i < n) wf[i] = __float2half_rn(W[i]);
}

// ============ fp16 single-term HMMA GEMM + bias ============
#define GPAD 40
__global__ __launch_bounds__(256) void gemm_f16(
    const __half* __restrict__ A, const __half* __restrict__ B,
    const float* __restrict__ b1, const float* __restrict__ b2,
    float* __restrict__ C, int N, int K)
{
    __shared__ __half sA[128][GPAD];
    __shared__ __half sB[128][GPAD];
    const int m0 = blockIdx.y * 128, n0 = blockIdx.x * 128;
    const int tid = threadIdx.x, wid = tid >> 5, lane = tid & 31;
    const int wm = wid & 3, wn = wid >> 2;
    const int g = lane >> 2, tq = lane & 3;

    float D[2][8][4];
    #pragma unroll
    for (int mt = 0; mt < 2; mt++)
        #pragma unroll
        for (int nt = 0; nt < 8; nt++)
            #pragma unroll
            for (int q = 0; q < 4; q++) D[mt][nt][q] = 0.0f;

    for (int kb = 0; kb < K; kb += 32) {
        #pragma unroll
        for (int i = 0; i < 2; i++) {
            int c = tid * 2 + i;
            int row = c >> 2, q = c & 3;
            *(uint4*)&sA[row][q * 8] = *(const uint4*)(A + (size_t)(m0 + row) * K + kb + q * 8);
            *(uint4*)&sB[row][q * 8] = *(const uint4*)(B + (size_t)(n0 + row) * K + kb + q * 8);
        }
        __syncthreads();
        #pragma unroll
        for (int kk = 0; kk < 2; kk++) {
            u32 ah[2][4], bh[8][2];
            #pragma unroll
            for (int mt = 0; mt < 2; mt++) {
                int r0 = wm * 32 + mt * 16 + g;
                int kc = kk * 16 + 2 * tq;
                ah[mt][0] = *(const u32*)&sA[r0][kc];
                ah[mt][1] = *(const u32*)&sA[r0 + 8][kc];
                ah[mt][2] = *(const u32*)&sA[r0][kc + 8];
                ah[mt][3] = *(const u32*)&sA[r0 + 8][kc + 8];
            }
            #pragma unroll
            for (int nt = 0; nt < 8; nt++) {
                int n_ = wn * 64 + nt * 8 + g;
                int kc = kk * 16 + 2 * tq;
                bh[nt][0] = *(const u32*)&sB[n_][kc];
                bh[nt][1] = *(const u32*)&sB[n_][kc + 8];
            }
            #pragma unroll
            for (int mt = 0; mt < 2; mt++)
                #pragma unroll
                for (int nt = 0; nt < 8; nt++)
                    mma_f16(D[mt][nt], ah[mt], bh[nt]);
        }
        __syncthreads();
    }
    #pragma unroll
    for (int mt = 0; mt < 2; mt++) {
        size_t r0 = (size_t)(m0 + wm * 32 + mt * 16 + g);
        size_t r1 = r0 + 8;
        #pragma unroll
        for (int nt = 0; nt < 8; nt++) {
            int c0 = n0 + wn * 64 + nt * 8 + 2 * tq;
            float bA = b1[c0] + b2[c0];
            float bB = b1[c0 + 1] + b2[c0 + 1];
            C[r0 * N + c0]     = D[mt][nt][0] + bA;
            C[r0 * N + c0 + 1] = D[mt][nt][1] + bB;
            C[r1 * N + c0]     = D[mt][nt][2] + bA;
            C[r1 * N + c0 + 1] = D[mt][nt][3] + bB;
        }
    }
}

// ============ Layer 2: H=64, CTA per chain; emits fp16 ============
#define L2_SMEM_BYTES (32 * 256 * 8 + 64 * 4 + 256 * 4)
__global__ __launch_bounds__(256, 1) void lstm2_kernel(
    const float* __restrict__ xg, const float* __restrict__ Whh,
    __half* __restrict__ y2f)
{
    extern __shared__ char smraw[];
    ull*   sW2 = (ull*)smraw;
    float* sh  = (float*)(smraw + 32 * 256 * 8);
    float* sg  = sh + 64;
    const int r = threadIdx.x;
    const int b = blockIdx.x >> 1, dir = blockIdx.x & 1;
    const int gate = r >> 6, j = r & 63;
    const float* WhhD = Whh + (size_t)dir * 256 * 64;

    for (int i = r; i < 32 * 256; i += 256) {
        int kp = i >> 8, rr = i & 255;
        sW2[i] = *(const ull*)(WhhD + rr * 64 + 2 * kp);
    }
    if (r < 64) sh[r] = 0.0f;
    float cc = 0.0f;
    __syncthreads();

    const float* xgb = xg + (size_t)b * TT * 512 + dir * 256 + r;
    const int t0 = dir ? (TT - 1) : 0;
    float xt = __ldg(xgb + (size_t)t0 * 512);

    for (int s = 0; s < TT; s++) {
        const int t = dir ? (TT - 1 - s) : s;
        float xnext = 0.0f;
        if (s + 1 < TT) {
            const int tn = dir ? (TT - 2 - s) : (s + 1);
            xnext = __ldg(xgb + (size_t)tn * 512);
        }
        ull accA = 0ull, accB = 0ull;
        #pragma unroll
        for (int kp = 0; kp < 32; kp += 2) {
            fma2(accA, sW2[kp * 256 + r],       *(const ull*)(sh + 2 * kp));
            fma2(accB, sW2[(kp + 1) * 256 + r], *(const ull*)(sh + 2 * kp + 2));
        }
        float alo, ahi, blo, bhi;
        upk(accA, alo, ahi); upk(accB, blo, bhi);
        float v = xt + (alo + ahi) + (blo + bhi);
        sg[r] = (gate == 2) ? mytanh(v) : mysig(v);
        __syncthreads();
        if (r < 64) {
            float i_ = sg[j], f_ = sg[j+64], gg = sg[j+128], o_ = sg[j+192];
            cc = fmaf(f_, cc, i_ * gg);
            float h = o_ * mytanh(cc);
            sh[j] = h;
            y2f[((size_t)b * TT + t) * 128 + dir * 64 + j] = __float2half_rn(h);
        }
        __syncthreads();
        xt = xnext;
    }
}

// ============ Layer 3 + mean: warp per chain ============
__global__ __launch_bounds__(256, 1) void lstm3_kernel(
    const float* __restrict__ xg, const float* __restrict__ Whh,
    float* __restrict__ s3)
{
    __shared__ float shh[8][16];
    const int tid = threadIdx.x, wid = tid >> 5, lane = tid & 31;
    const int pg = blockIdx.x * 8 + wid;
    const int b = pg >> 1, dir = pg & 1;
    const int r0 = lane, r1 = lane + 32;
    const float* WhhD = Whh + (size_t)dir * 64 * 16;
    float* shp = shh[wid];

    ull w0[8], w1[8];
    #pragma unroll
    for (int kp = 0; kp < 8; kp++) {
        w0[kp] = *(const ull*)(WhhD + r0 * 16 + 2 * kp);
        w1[kp] = *(const ull*)(WhhD + r1 * 16 + 2 * kp);
    }
    if (lane < 16) shp[lane] = 0.0f;
    float cc = 0.0f, sum = 0.0f;
    __syncwarp();

    const float* xgb = xg + (size_t)b * TT * 128 + dir * 64;
    const int t0 = dir ? (TT - 1) : 0;
    float xt0 = __ldg(xgb + (size_t)t0 * 128 + r0);
    float xt1 = __ldg(xgb + (size_t)t0 * 128 + r1);

    for (int s = 0; s < TT; s++) {
        float xn0 = 0.0f, xn1 = 0.0f;
        if (s + 1 < TT) {
            const int tn = dir ? (TT - 2 - s) : (s + 1);
            xn0 = __ldg(xgb + (size_t)tn * 128 + r0);
            xn1 = __ldg(xgb + (size_t)tn * 128 + r1);
        }
        ull a0 = 0ull, a1 = 0ull;
        #pragma unroll
        for (int kp = 0; kp < 8; kp++) {
            ull hb = *(const ull*)(shp + 2 * kp);
            fma2(a0, w0[kp], hb);
            fma2(a1, w1[kp], hb);
        }
        float l0, h0, l1, h1;
        upk(a0, l0, h0); upk(a1, l1, h1);
        float v0 = xt0 + l0 + h0, v1 = xt1 + l1 + h1;
        float g0 = mysig(v0);
        float g1 = (lane < 16) ? mytanh(v1) : mysig(v1);
        float f_ = __shfl_down_sync(0xffffffffu, g0, 16);
        float o_ = __shfl_down_sync(0xffffffffu, g1, 16);
        if (lane < 16) {
            cc = fmaf(f_, cc, g0 * g1);
            float h = o_ * mytanh(cc);
            shp[lane] = h;
            sum += h;
        }
        __syncwarp();
        xt0 = xn0; xt1 = xn1;
    }
    if (lane < 16) s3[b * 32 + dir * 16 + lane] = sum * (1.0f / TT);
}

// ============ MLP head ============
__global__ void mlp_kernel(
    const float* __restrict__ s3,
    const float* __restrict__ hW1, const float* __restrict__ hb1,
    const float* __restrict__ hW2, const float* __restrict__ hb2,
    const float* __restrict__ hW3, const float* __restrict__ hb3,
    float* __restrict__ out)
{
    int b = blockIdx.x * blockDim.x + threadIdx.x;
    if (b >= BB) return;
    float s[32];
    #pragma unroll
    for (int k = 0; k < 32; k++) s[k] = s3[b * 32 + k];
    float h1[64];
    for (int o = 0; o < 64; o++) {
        float a = hb1[o];
        #pragma unroll
        for (int k = 0; k < 32; k++) a = fmaf(s[k], hW1[o * 32 + k], a);
        h1[o] = fmaxf(a, 0.0f);
    }
    float h2[16];
    for (int o = 0; o < 16; o++) {
        float a = hb2[o];
        #pragma unroll
        for (int k = 0; k < 64; k++) a = fmaf(h1[k], hW2[o * 64 + k], a);
        h2[o] = fmaxf(a, 0.0f);
    }
    for (int o = 0; o < 20; o++) {
        float a = hb3[o];
        #pragma unroll
        for (int k = 0; k < 16; k++) a = fmaf(h2[k], hW3[o * 16 + k], a);
        out[b * 20 + o] = a;
    }
}

extern "C" void kernel_launch(void* const* d_in, const int* in_sizes, int n_in,
                              void* d_out, int out_size)
{
    const float* x    = (const float*)d_in[0];
    const float* Wih1 = (const float*)d_in[1];
    const float* Whh1 = (const float*)d_in[2];
    const float* bih1 = (const float*)d_in[3];
    const float* bhh1 = (const float*)d_in[4];
    const float* Wih2 = (const float*)d_in[5];
    const float* Whh2 = (const float*)d_in[6];
    const float* bih2 = (const float*)d_in[7];
    const float* bhh2 = (const float*)d_in[8];
    const float* Wih3 = (const float*)d_in[9];
    const float* Whh3 = (const float*)d_in[10];
    const float* bih3 = (const float*)d_in[11];
    const float* bhh3 = (const float*)d_in[12];
    const float* hW1  = (const float*)d_in[13];
    const float* hb1  = (const float*)d_in[14];
    const float* hW2  = (const float*)d_in[15];
    const float* hb2  = (const float*)d_in[16];
    const float* hW3  = (const float*)d_in[17];
    const float* hb3  = (const float*)d_in[18];
    float* out = (float*)d_out;

    __half *y1f, *w2f, *w3f, *y2f;
    float *xg2, *xg3, *s3;
    cudaGetSymbolAddress((void**)&y1f, g_y1f);
    cudaGetSymbolAddress((void**)&w2f, g_w2f);
    cudaGetSymbolAddress((void**)&w3f, g_w3f);
    cudaGetSymbolAddress((void**)&y2f, g_y2f);
    cudaGetSymbolAddress((void**)&xg2, g_xg2);
    cudaGetSymbolAddress((void**)&xg3, g_xg3);
    cudaGetSymbolAddress((void**)&s3,  g_sum3);

    static bool attr_set = false;
    if (!attr_set) {
        cudaFuncSetAttribute(lstm1_mma,
            cudaFuncAttributeMaxDynamicSharedMemorySize, L1_SMEM);
        cudaFuncSetAttribute(lstm2_kernel,
            cudaFuncAttributeMaxDynamicSharedMemorySize, L2_SMEM_BYTES);
        attr_set = true;
    }

    const int M = BB * TT;
    wconv_kernel<<<512, 256>>>(Wih2, w2f, 512 * 256);
    wconv_kernel<<<64, 256>>>(Wih3, w3f, 128 * 128);
    lstm1_mma<<<dim3(64, 2), 512, L1_SMEM>>>(x, Wih1, Whh1, bih1, bhh1, y1f);
    gemm_f16<<<dim3(4, M / 128), 256>>>(y1f, w2f, bih2, bhh2, xg2, 512, 256);
    lstm2_kernel<<<512, 256, L2_SMEM_BYTES>>>(xg2, Whh2, y2f);
    gemm_f16<<<dim3(1, M / 128), 256>>>(y2f, w3f, bih3, bhh3, xg3, 128, 128);
    lstm3_kernel<<<64, 256>>>(xg3, Whh3, s3);
    mlp_kernel<<<1, 256>>>(s3, hW1, hb1, hW2, hb2, hW3, hb3, out);
}

// round 16
// speedup vs baseline: 1.6371x; 1.1311x over previous
#include <cuda_runtime.h>
#include <cuda_fp16.h>
#include <math.h>

#define BB 256
#define TT 2048
typedef unsigned long long ull;
typedef unsigned int u32;

__device__ __half g_y1f[(size_t)BB * TT * 256];
__device__ __half g_w2f[512 * 256];
__device__ __half g_w3f[128 * 128];
__device__ __half g_y2f[(size_t)BB * TT * 128];
__device__ float g_xg2[(size_t)BB * TT * 512];
__device__ float g_xg3[(size_t)BB * TT * 128];
__device__ float g_sum3[BB * 32];

__device__ __forceinline__ float mysig(float v){ return __fdividef(1.0f, 1.0f + __expf(-v)); }
__device__ __forceinline__ float mytanh(float v){
    float e = __expf(2.0f * v);
    return 1.0f - 2.0f * __fdividef(1.0f, 1.0f + e);
}
__device__ __forceinline__ void upk(ull v, float& lo, float& hi){
    asm("mov.b64 {%0, %1}, %2;" : "=f"(lo), "=f"(hi) : "l"(v));
}
__device__ __forceinline__ void fma2(ull& d, ull a, ull b){
    asm("fma.rn.f32x2 %0, %1, %2, %0;" : "+l"(d) : "l"(a), "l"(b));
}
__device__ __forceinline__ void mma_f16(float* d, const u32* a, const u32* b){
    asm volatile("mma.sync.aligned.m16n8k16.row.col.f32.f16.f16.f32 "
        "{%0,%1,%2,%3}, {%4,%5,%6,%7}, {%8,%9}, {%0,%1,%2,%3};"
        : "+f"(d[0]), "+f"(d[1]), "+f"(d[2]), "+f"(d[3])
        : "r"(a[0]), "r"(a[1]), "r"(a[2]), "r"(a[3]), "r"(b[0]), "r"(b[1]));
}
__device__ __forceinline__ u32 h2u(float a, float b){
    __half2 t = __floats2half2_rn(a, b);
    return *(u32*)&t;
}

// ============ Layer 1: fp16 MMA, 8 batches/CTA (full N=8), grid (32,2) =====
#define L1_BHI  0          // fp16 B plane: [8 ks][32 l][2 u32] = 2KB
#define L1_GAT  2048       // float[512][9] = 18432B
#define L1_SMEM 20480

__global__ __launch_bounds__(512, 1) void lstm1_mma(
    const float* __restrict__ x, const float* __restrict__ Wih,
    const float* __restrict__ Whh, const float* __restrict__ bih,
    const float* __restrict__ bhh,
    __half* __restrict__ y1f)
{
    extern __shared__ char sm[];
    float* sgat = (float*)(sm + L1_GAT);

    const int tid = threadIdx.x, w = tid >> 5, l = tid & 31;
    const int g = l >> 2, tq = l & 3;
    const int dir = blockIdx.y, bg0 = blockIdx.x * 8;
    const float* WD = Whh + (size_t)dir * 512 * 128;

    u32 Ah[2][8][4];
    #pragma unroll
    for (int mt = 0; mt < 2; mt++)
        #pragma unroll
        for (int ks = 0; ks < 8; ks++) {
            int R = 32 * w + 16 * mt + g, C = 16 * ks + 2 * tq;
            const float* p0 = WD + (size_t)R * 128 + C;
            const float* p1 = WD + (size_t)(R + 8) * 128 + C;
            Ah[mt][ks][0] = h2u(p0[0], p0[1]);
            Ah[mt][ks][1] = h2u(p1[0], p1[1]);
            Ah[mt][ks][2] = h2u(p0[8], p0[9]);
            Ah[mt][ks][3] = h2u(p1[8], p1[9]);
        }
    ((u32*)(sm + L1_BHI))[tid] = 0;

    // combine roles: thread owns (cb0, j) and (cb1=cb0+4, j)
    const int cb0 = tid >> 7, cb1 = cb0 + 4, j = tid & 127;
    float bias4[4], wx04[4], wx14[4];
    #pragma unroll
    for (int q = 0; q < 4; q++) {
        int rq = j + 128 * q;
        bias4[q] = bih[dir * 512 + rq] + bhh[dir * 512 + rq];
        wx04[q] = Wih[dir * 1024 + rq * 2];
        wx14[q] = Wih[dir * 1024 + rq * 2 + 1];
    }
    const u32 bko0 = (u32)(j >> 4) * 256 + (u32)(4 * cb0 + ((j & 7) >> 1)) * 8
                   + (u32)((j >> 3) & 1) * 4 + (u32)(j & 1) * 2;
    const u32 bko1 = (u32)(j >> 4) * 256 + (u32)(4 * cb1 + ((j & 7) >> 1)) * 8
                   + (u32)((j >> 3) & 1) * 4 + (u32)(j & 1) * 2;
    float cc0 = 0.0f, cc1 = 0.0f;
    __syncthreads();

    for (int s = 0; s < TT; s++) {
        const int t = dir ? (TT - 1 - s) : s;
        float2 xv0 = __ldg((const float2*)(x + ((size_t)(bg0 + cb0) * TT + t) * 2));
        float2 xv1 = __ldg((const float2*)(x + ((size_t)(bg0 + cb1) * TT + t) * 2));

        float D0[4] = {0.f, 0.f, 0.f, 0.f};
        float D1[4] = {0.f, 0.f, 0.f, 0.f};
        #pragma unroll
        for (int ks = 0; ks < 8; ks++) {
            uint2 bh = *(const uint2*)(sm + L1_BHI + ks * 256 + l * 8);
            mma_f16(D0, Ah[0][ks], &bh.x);
            mma_f16(D1, Ah[1][ks], &bh.x);
        }
        {
            int r0 = 32 * w + g;
            sgat[r0 * 9 + tq * 2]            = D0[0];
            sgat[r0 * 9 + tq * 2 + 1]        = D0[1];
            sgat[(r0 + 8) * 9 + tq * 2]      = D0[2];
            sgat[(r0 + 8) * 9 + tq * 2 + 1]  = D0[3];
            sgat[(r0 + 16) * 9 + tq * 2]     = D1[0];
            sgat[(r0 + 16) * 9 + tq * 2 + 1] = D1[1];
            sgat[(r0 + 24) * 9 + tq * 2]     = D1[2];
            sgat[(r0 + 24) * 9 + tq * 2 + 1] = D1[3];
        }
        __syncthreads();

        {
            float vi0 = sgat[j * 9 + cb0]         + bias4[0] + wx04[0] * xv0.x + wx14[0] * xv0.y;
            float vf0 = sgat[(j + 128) * 9 + cb0] + bias4[1] + wx04[1] * xv0.x + wx14[1] * xv0.y;
            float vg0 = sgat[(j + 256) * 9 + cb0] + bias4[2] + wx04[2] * xv0.x + wx14[2] * xv0.y;
            float vo0 = sgat[(j + 384) * 9 + cb0] + bias4[3] + wx04[3] * xv0.x + wx14[3] * xv0.y;
            float vi1 = sgat[j * 9 + cb1]         + bias4[0] + wx04[0] * xv1.x + wx14[0] * xv1.y;
            float vf1 = sgat[(j + 128) * 9 + cb1] + bias4[1] + wx04[1] * xv1.x + wx14[1] * xv1.y;
            float vg1 = sgat[(j + 256) * 9 + cb1] + bias4[2] + wx04[2] * xv1.x + wx14[2] * xv1.y;
            float vo1 = sgat[(j + 384) * 9 + cb1] + bias4[3] + wx04[3] * xv1.x + wx14[3] * xv1.y;
            cc0 = fmaf(mysig(vf0), cc0, mysig(vi0) * mytanh(vg0));
            cc1 = fmaf(mysig(vf1), cc1, mysig(vi1) * mytanh(vg1));
            float h0 = mysig(vo0) * mytanh(cc0);
            float h1 = mysig(vo1) * mytanh(cc1);
            __half hf0 = __float2half_rn(h0);
            __half hf1 = __float2half_rn(h1);
            y1f[((size_t)(bg0 + cb0) * TT + t) * 256 + dir * 128 + j] = hf0;
            y1f[((size_t)(bg0 + cb1) * TT + t) * 256 + dir * 128 + j] = hf1;
            *(__half*)(sm + L1_BHI + bko0) = hf0;
            *(__half*)(sm + L1_BHI + bko1) = hf1;
        }
        __syncthreads();
    }
}

// ============ fp32 -> fp16 weight conversion ============
__global__ void wconv_kernel(const float* __restrict__ W,
    __half* __restrict__ wf, int n)
{
    int i = blockIdx.x * 256 + threadIdx.x;
    if (i < n) wf[i] = __float2half_rn(W[i]);
}

// ============ fp16 single-term HMMA GEMM + bias (R13 core) ============
#define GPAD 40
__global__ __launch_bounds__(256) void gemm_f16(
    const __half* __restrict__ A, const __half* __restrict__ B,
    const float* __restrict__ b1, const float* __restrict__ b2,
    float* __restrict__ C, int N, int K)
{
    __shared__ __half sA[128][GPAD];
    __shared__ __half sB[128][GPAD];
    const int m0 = blockIdx.y * 128, n0 = blockIdx.x * 128;
    const int tid = threadIdx.x, wid = tid >> 5, lane = tid & 31;
    const int wm = wid & 3, wn = wid >> 2;
    const int g = lane >> 2, tq = lane & 3;

    float D[2][8][4];
    #pragma unroll
    for (int mt = 0; mt < 2; mt++)
        #pragma unroll
        for (int nt = 0; nt < 8; nt++)
            #pragma unroll
            for (int q = 0; q < 4; q++) D[mt][nt][q] = 0.0f;

    for (int kb = 0; kb < K; kb += 32) {
        #pragma unroll
        for (int i = 0; i < 2; i++) {
            int c = tid * 2 + i;
            int row = c >> 2, q = c & 3;
            *(uint4*)&sA[row][q * 8] = *(const uint4*)(A + (size_t)(m0 + row) * K + kb + q * 8);
            *(uint4*)&sB[row][q * 8] = *(const uint4*)(B + (size_t)(n0 + row) * K + kb + q * 8);
        }
        __syncthreads();
        #pragma unroll
        for (int kk = 0; kk < 2; kk++) {
            u32 ah[2][4], bh[8][2];
            #pragma unroll
            for (int mt = 0; mt < 2; mt++) {
                int r0 = wm * 32 + mt * 16 + g;
                int kc = kk * 16 + 2 * tq;
                ah[mt][0] = *(const u32*)&sA[r0][kc];
                ah[mt][1] = *(const u32*)&sA[r0 + 8][kc];
                ah[mt][2] = *(const u32*)&sA[r0][kc + 8];
                ah[mt][3] = *(const u32*)&sA[r0 + 8][kc + 8];
            }
            #pragma unroll
            for (int nt = 0; nt < 8; nt++) {
                int n_ = wn * 64 + nt * 8 + g;
                int kc = kk * 16 + 2 * tq;
                bh[nt][0] = *(const u32*)&sB[n_][kc];
                bh[nt][1] = *(const u32*)&sB[n_][kc + 8];
            }
            #pragma unroll
            for (int mt = 0; mt < 2; mt++)
                #pragma unroll
                for (int nt = 0; nt < 8; nt++)
                    mma_f16(D[mt][nt], ah[mt], bh[nt]);
        }
        __syncthreads();
    }
    #pragma unroll
    for (int mt = 0; mt < 2; mt++) {
        size_t r0 = (size_t)(m0 + wm * 32 + mt * 16 + g);
        size_t r1 = r0 + 8;
        #pragma unroll
        for (int nt = 0; nt < 8; nt++) {
            int c0 = n0 + wn * 64 + nt * 8 + 2 * tq;
            float bA = b1[c0] + b2[c0];
            float bB = b1[c0 + 1] + b2[c0 + 1];
            C[r0 * N + c0]     = D[mt][nt][0] + bA;
            C[r0 * N + c0 + 1] = D[mt][nt][1] + bB;
            C[r1 * N + c0]     = D[mt][nt][2] + bA;
            C[r1 * N + c0 + 1] = D[mt][nt][3] + bB;
        }
    }
}

// ============ Layer 2: 2 chains/CTA sharing weight LDS; emits fp16 ============
#define L2_SMEM_BYTES (32 * 256 * 8 + 128 * 4 + 512 * 4)
__global__ __launch_bounds__(256, 1) void lstm2_kernel(
    const float* __restrict__ xg, const float* __restrict__ Whh,
    __half* __restrict__ y2f)
{
    extern __shared__ char smraw[];
    ull*   sW2 = (ull*)smraw;                       // [32 kp][256 r]
    float* sh  = (float*)(smraw + 32 * 256 * 8);    // [2][64]
    float* sg  = sh + 128;                          // [2][256]
    const int r = threadIdx.x;
    const int bp  = blockIdx.x >> 1;                // batch pair
    const int dir = blockIdx.x & 1;
    const int b0 = bp * 2, b1 = bp * 2 + 1;
    const int gate = r >> 6;
    const float* WhhD = Whh + (size_t)dir * 256 * 64;

    for (int i = r; i < 32 * 256; i += 256) {
        int kp = i >> 8, rr = i & 255;
        sW2[i] = *(const ull*)(WhhD + rr * 64 + 2 * kp);
    }
    if (r < 128) sh[r] = 0.0f;
    float cc = 0.0f;                                 // thread r<128 owns (chain r>>6, unit r&63)
    __syncthreads();

    const float* xgb0 = xg + (size_t)b0 * TT * 512 + dir * 256 + r;
    const float* xgb1 = xg + (size_t)b1 * TT * 512 + dir * 256 + r;
    const int t0 = dir ? (TT - 1) : 0;
    float xt0 = __ldg(xgb0 + (size_t)t0 * 512);
    float xt1 = __ldg(xgb1 + (size_t)t0 * 512);

    for (int s = 0; s < TT; s++) {
        const int t = dir ? (TT - 1 - s) : s;
        float xn0 = 0.0f, xn1 = 0.0f;
        if (s + 1 < TT) {
            const int tn = dir ? (TT - 2 - s) : (s + 1);
            xn0 = __ldg(xgb0 + (size_t)tn * 512);
            xn1 = __ldg(xgb1 + (size_t)tn * 512);
        }
        ull a0 = 0ull, a1 = 0ull;
        #pragma unroll
        for (int kp = 0; kp < 32; kp++) {
            ull wv = sW2[kp * 256 + r];
            fma2(a0, wv, *(const ull*)(sh + 2 * kp));
            fma2(a1, wv, *(const ull*)(sh + 64 + 2 * kp));
        }
        float l0, h0, l1, h1;
        upk(a0, l0, h0); upk(a1, l1, h1);
        float v0 = xt0 + l0 + h0;
        float v1 = xt1 + l1 + h1;
        if (gate == 2) { sg[r] = mytanh(v0); sg[256 + r] = mytanh(v1); }
        else           { sg[r] = mysig(v0);  sg[256 + r] = mysig(v1); }
        __syncthreads();
        if (r < 128) {
            int ch = r >> 6, jj = r & 63;
            const float* sgc = sg + ch * 256;
            float i_ = sgc[jj], f_ = sgc[jj + 64], gg = sgc[jj + 128], o_ = sgc[jj + 192];
            cc = fmaf(f_, cc, i_ * gg);
            float h = o_ * mytanh(cc);
            sh[ch * 64 + jj] = h;
            y2f[((size_t)(b0 + ch) * TT + t) * 128 + dir * 64 + jj] = __float2half_rn(h);
        }
        __syncthreads();
        xt0 = xn0; xt1 = xn1;
    }
}

// ============ Layer 3 + mean: warp per chain ============
__global__ __launch_bounds__(256, 1) void lstm3_kernel(
    const float* __restrict__ xg, const float* __restrict__ Whh,
    float* __restrict__ s3)
{
    __shared__ float shh[8][16];
    const int tid = threadIdx.x, wid = tid >> 5, lane = tid & 31;
    const int pg = blockIdx.x * 8 + wid;
    const int b = pg >> 1, dir = pg & 1;
    const int r0 = lane, r1 = lane + 32;
    const float* WhhD = Whh + (size_t)dir * 64 * 16;
    float* shp = shh[wid];

    ull w0[8], w1[8];
    #pragma unroll
    for (int kp = 0; kp < 8; kp++) {
        w0[kp] = *(const ull*)(WhhD + r0 * 16 + 2 * kp);
        w1[kp] = *(const ull*)(WhhD + r1 * 16 + 2 * kp);
    }
    if (lane < 16) shp[lane] = 0.0f;
    float cc = 0.0f, sum = 0.0f;
    __syncwarp();

    const float* xgb = xg + (size_t)b * TT * 128 + dir * 64;
    const int t0 = dir ? (TT - 1) : 0;
    float xt0 = __ldg(xgb + (size_t)t0 * 128 + r0);
    float xt1 = __ldg(xgb + (size_t)t0 * 128 + r1);

    for (int s = 0; s < TT; s++) {
        float xn0 = 0.0f, xn1 = 0.0f;
        if (s + 1 < TT) {
            const int tn = dir ? (TT - 2 - s) : (s + 1);
            xn0 = __ldg(xgb + (size_t)tn * 128 + r0);
            xn1 = __ldg(xgb + (size_t)tn * 128 + r1);
        }
        ull a0 = 0ull, a1 = 0ull;
        #pragma unroll
        for (int kp = 0; kp < 8; kp++) {
            ull hb = *(const ull*)(shp + 2 * kp);
            fma2(a0, w0[kp], hb);
            fma2(a1, w1[kp], hb);
        }
        float l0, h0, l1, h1;
        upk(a0, l0, h0); upk(a1, l1, h1);
        float v0 = xt0 + l0 + h0, v1 = xt1 + l1 + h1;
        float g0 = mysig(v0);
        float g1 = (lane < 16) ? mytanh(v1) : mysig(v1);
        float f_ = __shfl_down_sync(0xffffffffu, g0, 16);
        float o_ = __shfl_down_sync(0xffffffffu, g1, 16);
        if (lane < 16) {
            cc = fmaf(f_, cc, g0 * g1);
            float h = o_ * mytanh(cc);
            shp[lane] = h;
            sum += h;
        }
        __syncwarp();
        xt0 = xn0; xt1 = xn1;
    }
    if (lane < 16) s3[b * 32 + dir * 16 + lane] = sum * (1.0f / TT);
}

// ============ MLP head ============
__global__ void mlp_kernel(
    const float* __restrict__ s3,
    const float* __restrict__ hW1, const float* __restrict__ hb1,
    const float* __restrict__ hW2, const float* __restrict__ hb2,
    const float* __restrict__ hW3, const float* __restrict__ hb3,
    float* __restrict__ out)
{
    int b = blockIdx.x * blockDim.x + threadIdx.x;
    if (b >= BB) return;
    float s[32];
    #pragma unroll
    for (int k = 0; k < 32; k++) s[k] = s3[b * 32 + k];
    float h1[64];
    for (int o = 0; o < 64; o++) {
        float a = hb1[o];
        #pragma unroll
        for (int k = 0; k < 32; k++) a = fmaf(s[k], hW1[o * 32 + k], a);
        h1[o] = fmaxf(a, 0.0f);
    }
    float h2[16];
    for (int o = 0; o < 16; o++) {
        float a = hb2[o];
        #pragma unroll
        for (int k = 0; k < 64; k++) a = fmaf(h1[k], hW2[o * 64 + k], a);
        h2[o] = fmaxf(a, 0.0f);
    }
    for (int o = 0; o < 20; o++) {
        float a = hb3[o];
        #pragma unroll
        for (int k = 0; k < 16; k++) a = fmaf(h2[k], hW3[o * 16 + k], a);
        out[b * 20 + o] = a;
    }
}

extern "C" void kernel_launch(void* const* d_in, const int* in_sizes, int n_in,
                              void* d_out, int out_size)
{
    const float* x    = (const float*)d_in[0];
    const float* Wih1 = (const float*)d_in[1];
    const float* Whh1 = (const float*)d_in[2];
    const float* bih1 = (const float*)d_in[3];
    const float* bhh1 = (const float*)d_in[4];
    const float* Wih2 = (const float*)d_in[5];
    const float* Whh2 = (const float*)d_in[6];
    const float* bih2 = (const float*)d_in[7];
    const float* bhh2 = (const float*)d_in[8];
    const float* Wih3 = (const float*)d_in[9];
    const float* Whh3 = (const float*)d_in[10];
    const float* bih3 = (const float*)d_in[11];
    const float* bhh3 = (const float*)d_in[12];
    const float* hW1  = (const float*)d_in[13];
    const float* hb1  = (const float*)d_in[14];
    const float* hW2  = (const float*)d_in[15];
    const float* hb2  = (const float*)d_in[16];
    const float* hW3  = (const float*)d_in[17];
    const float* hb3  = (const float*)d_in[18];
    float* out = (float*)d_out;

    __half *y1f, *w2f, *w3f, *y2f;
    float *xg2, *xg3, *s3;
    cudaGetSymbolAddress((void**)&y1f, g_y1f);
    cudaGetSymbolAddress((void**)&w2f, g_w2f);
    cudaGetSymbolAddress((void**)&w3f, g_w3f);
    cudaGetSymbolAddress((void**)&y2f, g_y2f);
    cudaGetSymbolAddress((void**)&xg2, g_xg2);
    cudaGetSymbolAddress((void**)&xg3, g_xg3);
    cudaGetSymbolAddress((void**)&s3,  g_sum3);

    static bool attr_set = false;
    if (!attr_set) {
        cudaFuncSetAttribute(lstm1_mma,
            cudaFuncAttributeMaxDynamicSharedMemorySize, L1_SMEM);
        cudaFuncSetAttribute(lstm2_kernel,
            cudaFuncAttributeMaxDynamicSharedMemorySize, L2_SMEM_BYTES);
        attr_set = true;
    }

    const int M = BB * TT;
    wconv_kernel<<<512, 256>>>(Wih2, w2f, 512 * 256);
    wconv_kernel<<<64, 256>>>(Wih3, w3f, 128 * 128);
    lstm1_mma<<<dim3(32, 2), 512, L1_SMEM>>>(x, Wih1, Whh1, bih1, bhh1, y1f);
    gemm_f16<<<dim3(4, M / 128), 256>>>(y1f, w2f, bih2, bhh2, xg2, 512, 256);
    lstm2_kernel<<<256, 256, L2_SMEM_BYTES>>>(xg2, Whh2, y2f);
    gemm_f16<<<dim3(1, M / 128), 256>>>(y2f, w3f, bih3, bhh3, xg3, 128, 128);
    lstm3_kernel<<<64, 256>>>(xg3, Whh3, s3);
    mlp_kernel<<<1, 256>>>(s3, hW1, hb1, hW2, hb2, hW3, hb3, out);
}

// round 17
// speedup vs baseline: 1.8541x; 1.1326x over previous
#include <cuda_runtime.h>
#include <cuda_fp16.h>
#include <math.h>

#define BB 256
#define TT 2048
typedef unsigned long long ull;
typedef unsigned int u32;

__device__ __half g_y1f[(size_t)BB * TT * 256];
__device__ __half g_w2f[512 * 256];
__device__ __half g_w3f[128 * 128];
__device__ __half g_y2f[(size_t)BB * TT * 128];
__device__ float g_xg2[(size_t)BB * TT * 512];
__device__ float g_xg3[(size_t)BB * TT * 128];
__device__ float g_sum3[BB * 32];

__device__ __forceinline__ float tanha(float v){
    float r; asm("tanh.approx.f32 %0, %1;" : "=f"(r) : "f"(v)); return r;
}
__device__ __forceinline__ float siga(float v){
    float r; asm("tanh.approx.f32 %0, %1;" : "=f"(r) : "f"(0.5f * v));
    return fmaf(0.5f, r, 0.5f);
}
__device__ __forceinline__ void upk(ull v, float& lo, float& hi){
    asm("mov.b64 {%0, %1}, %2;" : "=f"(lo), "=f"(hi) : "l"(v));
}
__device__ __forceinline__ void fma2(ull& d, ull a, ull b){
    asm("fma.rn.f32x2 %0, %1, %2, %0;" : "+l"(d) : "l"(a), "l"(b));
}
__device__ __forceinline__ void mma_f16(float* d, const u32* a, const u32* b){
    asm volatile("mma.sync.aligned.m16n8k16.row.col.f32.f16.f16.f32 "
        "{%0,%1,%2,%3}, {%4,%5,%6,%7}, {%8,%9}, {%0,%1,%2,%3};"
        : "+f"(d[0]), "+f"(d[1]), "+f"(d[2]), "+f"(d[3])
        : "r"(a[0]), "r"(a[1]), "r"(a[2]), "r"(a[3]), "r"(b[0]), "r"(b[1]));
}
__device__ __forceinline__ u32 h2u(float a, float b){
    __half2 t = __floats2half2_rn(a, b);
    return *(u32*)&t;
}

// ============ Layer 1: fp16 MMA, 8 batches/CTA (full N=8), grid (32,2) =====
#define L1_BHI  0          // fp16 B plane: [8 ks][32 l][2 u32] = 2KB
#define L1_GAT  2048       // float[512][9] = 18432B
#define L1_SMEM 20480

__global__ __launch_bounds__(512, 1) void lstm1_mma(
    const float* __restrict__ x, const float* __restrict__ Wih,
    const float* __restrict__ Whh, const float* __restrict__ bih,
    const float* __restrict__ bhh,
    __half* __restrict__ y1f)
{
    extern __shared__ char sm[];
    float* sgat = (float*)(sm + L1_GAT);

    const int tid = threadIdx.x, w = tid >> 5, l = tid & 31;
    const int g = l >> 2, tq = l & 3;
    const int dir = blockIdx.y, bg0 = blockIdx.x * 8;
    const float* WD = Whh + (size_t)dir * 512 * 128;

    u32 Ah[2][8][4];
    #pragma unroll
    for (int mt = 0; mt < 2; mt++)
        #pragma unroll
        for (int ks = 0; ks < 8; ks++) {
            int R = 32 * w + 16 * mt + g, C = 16 * ks + 2 * tq;
            const float* p0 = WD + (size_t)R * 128 + C;
            const float* p1 = WD + (size_t)(R + 8) * 128 + C;
            Ah[mt][ks][0] = h2u(p0[0], p0[1]);
            Ah[mt][ks][1] = h2u(p1[0], p1[1]);
            Ah[mt][ks][2] = h2u(p0[8], p0[9]);
            Ah[mt][ks][3] = h2u(p1[8], p1[9]);
        }
    ((u32*)(sm + L1_BHI))[tid] = 0;

    const int cb0 = tid >> 7, cb1 = cb0 + 4, j = tid & 127;
    float bias4[4], wx04[4], wx14[4];
    #pragma unroll
    for (int q = 0; q < 4; q++) {
        int rq = j + 128 * q;
        bias4[q] = bih[dir * 512 + rq] + bhh[dir * 512 + rq];
        wx04[q] = Wih[dir * 1024 + rq * 2];
        wx14[q] = Wih[dir * 1024 + rq * 2 + 1];
    }
    const u32 bko0 = (u32)(j >> 4) * 256 + (u32)(4 * cb0 + ((j & 7) >> 1)) * 8
                   + (u32)((j >> 3) & 1) * 4 + (u32)(j & 1) * 2;
    const u32 bko1 = (u32)(j >> 4) * 256 + (u32)(4 * cb1 + ((j & 7) >> 1)) * 8
                   + (u32)((j >> 3) & 1) * 4 + (u32)(j & 1) * 2;
    float cc0 = 0.0f, cc1 = 0.0f;
    __syncthreads();

    for (int s = 0; s < TT; s++) {
        const int t = dir ? (TT - 1 - s) : s;
        float2 xv0 = __ldg((const float2*)(x + ((size_t)(bg0 + cb0) * TT + t) * 2));
        float2 xv1 = __ldg((const float2*)(x + ((size_t)(bg0 + cb1) * TT + t) * 2));

        float D0[4] = {0.f, 0.f, 0.f, 0.f};
        float D1[4] = {0.f, 0.f, 0.f, 0.f};
        #pragma unroll
        for (int ks = 0; ks < 8; ks++) {
            uint2 bh = *(const uint2*)(sm + L1_BHI + ks * 256 + l * 8);
            mma_f16(D0, Ah[0][ks], &bh.x);
            mma_f16(D1, Ah[1][ks], &bh.x);
        }
        {
            int r0 = 32 * w + g;
            sgat[r0 * 9 + tq * 2]            = D0[0];
            sgat[r0 * 9 + tq * 2 + 1]        = D0[1];
            sgat[(r0 + 8) * 9 + tq * 2]      = D0[2];
            sgat[(r0 + 8) * 9 + tq * 2 + 1]  = D0[3];
            sgat[(r0 + 16) * 9 + tq * 2]     = D1[0];
            sgat[(r0 + 16) * 9 + tq * 2 + 1] = D1[1];
            sgat[(r0 + 24) * 9 + tq * 2]     = D1[2];
            sgat[(r0 + 24) * 9 + tq * 2 + 1] = D1[3];
        }
        __syncthreads();

        {
            float vi0 = sgat[j * 9 + cb0]         + bias4[0] + wx04[0] * xv0.x + wx14[0] * xv0.y;
            float vf0 = sgat[(j + 128) * 9 + cb0] + bias4[1] + wx04[1] * xv0.x + wx14[1] * xv0.y;
            float vg0 = sgat[(j + 256) * 9 + cb0] + bias4[2] + wx04[2] * xv0.x + wx14[2] * xv0.y;
            float vo0 = sgat[(j + 384) * 9 + cb0] + bias4[3] + wx04[3] * xv0.x + wx14[3] * xv0.y;
            float vi1 = sgat[j * 9 + cb1]         + bias4[0] + wx04[0] * xv1.x + wx14[0] * xv1.y;
            float vf1 = sgat[(j + 128) * 9 + cb1] + bias4[1] + wx04[1] * xv1.x + wx14[1] * xv1.y;
            float vg1 = sgat[(j + 256) * 9 + cb1] + bias4[2] + wx04[2] * xv1.x + wx14[2] * xv1.y;
            float vo1 = sgat[(j + 384) * 9 + cb1] + bias4[3] + wx04[3] * xv1.x + wx14[3] * xv1.y;
            cc0 = fmaf(siga(vf0), cc0, siga(vi0) * tanha(vg0));
            cc1 = fmaf(siga(vf1), cc1, siga(vi1) * tanha(vg1));
            float h0 = siga(vo0) * tanha(cc0);
            float h1 = siga(vo1) * tanha(cc1);
            __half hf0 = __float2half_rn(h0);
            __half hf1 = __float2half_rn(h1);
            y1f[((size_t)(bg0 + cb0) * TT + t) * 256 + dir * 128 + j] = hf0;
            y1f[((size_t)(bg0 + cb1) * TT + t) * 256 + dir * 128 + j] = hf1;
            *(__half*)(sm + L1_BHI + bko0) = hf0;
            *(__half*)(sm + L1_BHI + bko1) = hf1;
        }
        __syncthreads();
    }
}

// ============ fp32 -> fp16 weight conversion ============
__global__ void wconv_kernel(const float* __restrict__ W,
    __half* __restrict__ wf, int n)
{
    int i = blockIdx.x * 256 + threadIdx.x;
    if (i < n) wf[i] = __float2half_rn(W[i]);
}

// ============ fp16 HMMA GEMM + bias, register double-buffered ============
#define GPAD 40
__global__ __launch_bounds__(256, 2) void gemm_f16(
    const __half* __restrict__ A, const __half* __restrict__ B,
    const float* __restrict__ b1, const float* __restrict__ b2,
    float* __restrict__ C, int N, int K)
{
    __shared__ __half sA[128][GPAD];
    __shared__ __half sB[128][GPAD];
    const int m0 = blockIdx.y * 128, n0 = blockIdx.x * 128;
    const int tid = threadIdx.x, wid = tid >> 5, lane = tid & 31;
    const int wm = wid & 3, wn = wid >> 2;
    const int g = lane >> 2, tq = lane & 3;
    const int c0r = (tid * 2) >> 2,     c0q = (tid * 2) & 3;
    const int c1r = (tid * 2 + 1) >> 2, c1q = (tid * 2 + 1) & 3;

    float D[2][8][4];
    #pragma unroll
    for (int mt = 0; mt < 2; mt++)
        #pragma unroll
        for (int nt = 0; nt < 8; nt++)
            #pragma unroll
            for (int q = 0; q < 4; q++) D[mt][nt][q] = 0.0f;

    uint4 pa0, pa1, pb0, pb1;
    pa0 = *(const uint4*)(A + (size_t)(m0 + c0r) * K + 0 + c0q * 8);
    pa1 = *(const uint4*)(A + (size_t)(m0 + c1r) * K + 0 + c1q * 8);
    pb0 = *(const uint4*)(B + (size_t)(n0 + c0r) * K + 0 + c0q * 8);
    pb1 = *(const uint4*)(B + (size_t)(n0 + c1r) * K + 0 + c1q * 8);

    const int nkb = K >> 5;
    for (int ib = 0; ib < nkb; ib++) {
        *(uint4*)&sA[c0r][c0q * 8] = pa0;
        *(uint4*)&sA[c1r][c1q * 8] = pa1;
        *(uint4*)&sB[c0r][c0q * 8] = pb0;
        *(uint4*)&sB[c1r][c1q * 8] = pb1;
        __syncthreads();
        if (ib + 1 < nkb) {
            int kb = (ib + 1) << 5;
            pa0 = *(const uint4*)(A + (size_t)(m0 + c0r) * K + kb + c0q * 8);
            pa1 = *(const uint4*)(A + (size_t)(m0 + c1r) * K + kb + c1q * 8);
            pb0 = *(const uint4*)(B + (size_t)(n0 + c0r) * K + kb + c0q * 8);
            pb1 = *(const uint4*)(B + (size_t)(n0 + c1r) * K + kb + c1q * 8);
        }
        #pragma unroll
        for (int kk = 0; kk < 2; kk++) {
            u32 ah[2][4], bh[8][2];
            #pragma unroll
            for (int mt = 0; mt < 2; mt++) {
                int r0 = wm * 32 + mt * 16 + g;
                int kc = kk * 16 + 2 * tq;
                ah[mt][0] = *(const u32*)&sA[r0][kc];
                ah[mt][1] = *(const u32*)&sA[r0 + 8][kc];
                ah[mt][2] = *(const u32*)&sA[r0][kc + 8];
                ah[mt][3] = *(const u32*)&sA[r0 + 8][kc + 8];
            }
            #pragma unroll
            for (int nt = 0; nt < 8; nt++) {
                int n_ = wn * 64 + nt * 8 + g;
                int kc = kk * 16 + 2 * tq;
                bh[nt][0] = *(const u32*)&sB[n_][kc];
                bh[nt][1] = *(const u32*)&sB[n_][kc + 8];
            }
            #pragma unroll
            for (int mt = 0; mt < 2; mt++)
                #pragma unroll
                for (int nt = 0; nt < 8; nt++)
                    mma_f16(D[mt][nt], ah[mt], bh[nt]);
        }
        __syncthreads();
    }
    #pragma unroll
    for (int mt = 0; mt < 2; mt++) {
        size_t r0 = (size_t)(m0 + wm * 32 + mt * 16 + g);
        size_t r1 = r0 + 8;
        #pragma unroll
        for (int nt = 0; nt < 8; nt++) {
            int c0 = n0 + wn * 64 + nt * 8 + 2 * tq;
            float bA = b1[c0] + b2[c0];
            float bB = b1[c0 + 1] + b2[c0 + 1];
            C[r0 * N + c0]     = D[mt][nt][0] + bA;
            C[r0 * N + c0 + 1] = D[mt][nt][1] + bB;
            C[r1 * N + c0]     = D[mt][nt][2] + bA;
            C[r1 * N + c0 + 1] = D[mt][nt][3] + bB;
        }
    }
}

// ============ Layer 2: 2 chains/CTA sharing weight LDS; emits fp16 ============
#define L2_SMEM_BYTES (32 * 256 * 8 + 128 * 4 + 512 * 4)
__global__ __launch_bounds__(256, 1) void lstm2_kernel(
    const float* __restrict__ xg, const float* __restrict__ Whh,
    __half* __restrict__ y2f)
{
    extern __shared__ char smraw[];
    ull*   sW2 = (ull*)smraw;
    float* sh  = (float*)(smraw + 32 * 256 * 8);
    float* sg  = sh + 128;
    const int r = threadIdx.x;
    const int bp  = blockIdx.x >> 1;
    const int dir = blockIdx.x & 1;
    const int b0 = bp * 2, b1 = bp * 2 + 1;
    const int gate = r >> 6;
    const float* WhhD = Whh + (size_t)dir * 256 * 64;

    for (int i = r; i < 32 * 256; i += 256) {
        int kp = i >> 8, rr = i & 255;
        sW2[i] = *(const ull*)(WhhD + rr * 64 + 2 * kp);
    }
    if (r < 128) sh[r] = 0.0f;
    float cc = 0.0f;
    __syncthreads();

    const float* xgb0 = xg + (size_t)b0 * TT * 512 + dir * 256 + r;
    const float* xgb1 = xg + (size_t)b1 * TT * 512 + dir * 256 + r;
    const int t0 = dir ? (TT - 1) : 0;
    float xt0 = __ldg(xgb0 + (size_t)t0 * 512);
    float xt1 = __ldg(xgb1 + (size_t)t0 * 512);

    for (int s = 0; s < TT; s++) {
        const int t = dir ? (TT - 1 - s) : s;
        float xn0 = 0.0f, xn1 = 0.0f;
        if (s + 1 < TT) {
            const int tn = dir ? (TT - 2 - s) : (s + 1);
            xn0 = __ldg(xgb0 + (size_t)tn * 512);
            xn1 = __ldg(xgb1 + (size_t)tn * 512);
        }
        ull a0 = 0ull, a1 = 0ull;
        #pragma unroll
        for (int kp = 0; kp < 32; kp++) {
            ull wv = sW2[kp * 256 + r];
            fma2(a0, wv, *(const ull*)(sh + 2 * kp));
            fma2(a1, wv, *(const ull*)(sh + 64 + 2 * kp));
        }
        float l0, h0, l1, h1;
        upk(a0, l0, h0); upk(a1, l1, h1);
        float v0 = xt0 + l0 + h0;
        float v1 = xt1 + l1 + h1;
        if (gate == 2) { sg[r] = tanha(v0); sg[256 + r] = tanha(v1); }
        else           { sg[r] = siga(v0);  sg[256 + r] = siga(v1); }
        __syncthreads();
        if (r < 128) {
            int ch = r >> 6, jj = r & 63;
            const float* sgc = sg + ch * 256;
            float i_ = sgc[jj], f_ = sgc[jj + 64], gg = sgc[jj + 128], o_ = sgc[jj + 192];
            cc = fmaf(f_, cc, i_ * gg);
            float h = o_ * tanha(cc);
            sh[ch * 64 + jj] = h;
            y2f[((size_t)(b0 + ch) * TT + t) * 128 + dir * 64 + jj] = __float2half_rn(h);
        }
        __syncthreads();
        xt0 = xn0; xt1 = xn1;
    }
}

// ============ Layer 3 + mean: warp per chain ============
__global__ __launch_bounds__(256, 1) void lstm3_kernel(
    const float* __restrict__ xg, const float* __restrict__ Whh,
    float* __restrict__ s3)
{
    __shared__ float shh[8][16];
    const int tid = threadIdx.x, wid = tid >> 5, lane = tid & 31;
    const int pg = blockIdx.x * 8 + wid;
    const int b = pg >> 1, dir = pg & 1;
    const int r0 = lane, r1 = lane + 32;
    const float* WhhD = Whh + (size_t)dir * 64 * 16;
    float* shp = shh[wid];

    ull w0[8], w1[8];
    #pragma unroll
    for (int kp = 0; kp < 8; kp++) {
        w0[kp] = *(const ull*)(WhhD + r0 * 16 + 2 * kp);
        w1[kp] = *(const ull*)(WhhD + r1 * 16 + 2 * kp);
    }
    if (lane < 16) shp[lane] = 0.0f;
    float cc = 0.0f, sum = 0.0f;
    __syncwarp();

    const float* xgb = xg + (size_t)b * TT * 128 + dir * 64;
    const int t0 = dir ? (TT - 1) : 0;
    float xt0 = __ldg(xgb + (size_t)t0 * 128 + r0);
    float xt1 = __ldg(xgb + (size_t)t0 * 128 + r1);

    for (int s = 0; s < TT; s++) {
        float xn0 = 0.0f, xn1 = 0.0f;
        if (s + 1 < TT) {
            const int tn = dir ? (TT - 2 - s) : (s + 1);
            xn0 = __ldg(xgb + (size_t)tn * 128 + r0);
            xn1 = __ldg(xgb + (size_t)tn * 128 + r1);
        }
        ull a0 = 0ull, a1 = 0ull;
        #pragma unroll
        for (int kp = 0; kp < 8; kp++) {
            ull hb = *(const ull*)(shp + 2 * kp);
            fma2(a0, w0[kp], hb);
            fma2(a1, w1[kp], hb);
        }
        float l0, h0, l1, h1;
        upk(a0, l0, h0); upk(a1, l1, h1);
        float v0 = xt0 + l0 + h0, v1 = xt1 + l1 + h1;
        float g0 = siga(v0);
        float g1 = (lane < 16) ? tanha(v1) : siga(v1);
        float f_ = __shfl_down_sync(0xffffffffu, g0, 16);
        float o_ = __shfl_down_sync(0xffffffffu, g1, 16);
        if (lane < 16) {
            cc = fmaf(f_, cc, g0 * g1);
            float h = o_ * tanha(cc);
            shp[lane] = h;
            sum += h;
        }
        __syncwarp();
        xt0 = xn0; xt1 = xn1;
    }
    if (lane < 16) s3[b * 32 + dir * 16 + lane] = sum * (1.0f / TT);
}

// ============ MLP head ============
__global__ void mlp_kernel(
    const float* __restrict__ s3,
    const float* __restrict__ hW1, const float* __restrict__ hb1,
    const float* __restrict__ hW2, const float* __restrict__ hb2,
    const float* __restrict__ hW3, const float* __restrict__ hb3,
    float* __restrict__ out)
{
    int b = blockIdx.x * blockDim.x + threadIdx.x;
    if (b >= BB) return;
    float s[32];
    #pragma unroll
    for (int k = 0; k < 32; k++) s[k] = s3[b * 32 + k];
    float h1[64];
    for (int o = 0; o < 64; o++) {
        float a = hb1[o];
        #pragma unroll
        for (int k = 0; k < 32; k++) a = fmaf(s[k], hW1[o * 32 + k], a);
        h1[o] = fmaxf(a, 0.0f);
    }
    float h2[16];
    for (int o = 0; o < 16; o++) {
        float a = hb2[o];
        #pragma unroll
        for (int k = 0; k < 64; k++) a = fmaf(h1[k], hW2[o * 64 + k], a);
        h2[o] = fmaxf(a, 0.0f);
    }
    for (int o = 0; o < 20; o++) {
        float a = hb3[o];
        #pragma unroll
        for (int k = 0; k < 16; k++) a = fmaf(h2[k], hW3[o * 16 + k], a);
        out[b * 20 + o] = a;
    }
}

extern "C" void kernel_launch(void* const* d_in, const int* in_sizes, int n_in,
                              void* d_out, int out_size)
{
    const float* x    = (const float*)d_in[0];
    const float* Wih1 = (const float*)d_in[1];
    const float* Whh1 = (const float*)d_in[2];
    const float* bih1 = (const float*)d_in[3];
    const float* bhh1 = (const float*)d_in[4];
    const float* Wih2 = (const float*)d_in[5];
    const float* Whh2 = (const float*)d_in[6];
    const float* bih2 = (const float*)d_in[7];
    const float* bhh2 = (const float*)d_in[8];
    const float* Wih3 = (const float*)d_in[9];
    const float* Whh3 = (const float*)d_in[10];
    const float* bih3 = (const float*)d_in[11];
    const float* bhh3 = (const float*)d_in[12];
    const float* hW1  = (const float*)d_in[13];
    const float* hb1  = (const float*)d_in[14];
    const float* hW2  = (const float*)d_in[15];
    const float* hb2  = (const float*)d_in[16];
    const float* hW3  = (const float*)d_in[17];
    const float* hb3  = (const float*)d_in[18];
    float* out = (float*)d_out;

    __half *y1f, *w2f, *w3f, *y2f;
    float *xg2, *xg3, *s3;
    cudaGetSymbolAddress((void**)&y1f, g_y1f);
    cudaGetSymbolAddress((void**)&w2f, g_w2f);
    cudaGetSymbolAddress((void**)&w3f, g_w3f);
    cudaGetSymbolAddress((void**)&y2f, g_y2f);
    cudaGetSymbolAddress((void**)&xg2, g_xg2);
    cudaGetSymbolAddress((void**)&xg3, g_xg3);
    cudaGetSymbolAddress((void**)&s3,  g_sum3);

    static bool attr_set = false;
    if (!attr_set) {
        cudaFuncSetAttribute(lstm1_mma,
            cudaFuncAttributeMaxDynamicSharedMemorySize, L1_SMEM);
        cudaFuncSetAttribute(lstm2_kernel,
            cudaFuncAttributeMaxDynamicSharedMemorySize, L2_SMEM_BYTES);
        attr_set = true;
    }

    const int M = BB * TT;
    wconv_kernel<<<512, 256>>>(Wih2, w2f, 512 * 256);
    wconv_kernel<<<64, 256>>>(Wih3, w3f, 128 * 128);
    lstm1_mma<<<dim3(32, 2), 512, L1_SMEM>>>(x, Wih1, Whh1, bih1, bhh1, y1f);
    gemm_f16<<<dim3(4, M / 128), 256>>>(y1f, w2f, bih2, bhh2, xg2, 512, 256);
    lstm2_kernel<<<256, 256, L2_SMEM_BYTES>>>(xg2, Whh2, y2f);
    gemm_f16<<<dim3(1, M / 128), 256>>>(y2f, w3f, bih3, bhh3, xg3, 128, 128);
    lstm3_kernel<<<64, 256>>>(xg3, Whh3, s3);
    mlp_kernel<<<1, 256>>>(s3, hW1, hb1, hW2, hb2, hW3, hb3, out);
}